// round 4
// baseline (speedup 1.0000x reference)
#include <cuda_runtime.h>
#include <math.h>

#define Bn   8
#define Mn   8192
#define Sn   128
#define Dn   512
#define Qn   32
#define Hn   8
#define HDn  64
#define RROWS 256          // Hn*Qn rows per batch
#define SCALE 0.125f       // 1/sqrt(64)

// ---- output section offsets (floats) ----
#define OUT_READ  0
#define OUT_ATTN  131072
#define OUT_GATE  2228224
#define OUT_QUER  2228480

// ---------------- scratch (__device__ globals; no allocation) ----------------
__device__ float g_pooled[Bn*Dn];
__device__ float g_cvec[Bn*Dn];
__device__ float g_queries[Bn*Qn*Dn];
__device__ float g_qh[Bn*Qn*Dn];
__device__ float g_qk[Bn*RROWS*Dn];
__device__ float g_sbias[Bn*RROWS];
__device__ float g_attn[(size_t)Bn*RROWS*Mn];     // 64 MB: scores -> attn
__device__ float g_AM[Hn*Bn*Qn*Dn];               // [h][b][q][d]
__device__ float g_ctx[Bn*Qn*Dn];
__device__ float g_read[Bn*Qn*Dn];
__device__ float g_gates[Bn*Qn];
__device__ unsigned char g_maskb[Bn*Mn];
__device__ int g_maskmode;

// ---------------- tf32 helpers ----------------
__device__ __forceinline__ void split_tf32(float x, unsigned &hi, unsigned &lo) {
    float h; asm("cvt.rna.tf32.f32 %0, %1;" : "=f"(h) : "f"(x));
    float l = x - h;
    float l2; asm("cvt.rna.tf32.f32 %0, %1;" : "=f"(l2) : "f"(l));
    hi = __float_as_uint(h);
    lo = __float_as_uint(l2);
}

__device__ __forceinline__ void mma_tf32(float* c, const unsigned* a, const unsigned* b) {
    asm volatile("mma.sync.aligned.m16n8k8.row.col.f32.tf32.tf32.f32 "
        "{%0,%1,%2,%3}, {%4,%5,%6,%7}, {%8,%9}, {%0,%1,%2,%3};\n"
        : "+f"(c[0]), "+f"(c[1]), "+f"(c[2]), "+f"(c[3])
        : "r"(a[0]), "r"(a[1]), "r"(a[2]), "r"(a[3]), "r"(b[0]), "r"(b[1]));
}

// ---------------- mask dtype sniffer + normalizer ----------------
__global__ void k_detect(const unsigned char* __restrict__ p) {
    __shared__ int viI, viF;
    if (threadIdx.x == 0) { viI = 0; viF = 0; }
    __syncthreads();
    const unsigned int* w = (const unsigned int*)p;
    for (int i = threadIdx.x; i < 4096; i += blockDim.x) {
        unsigned int v = w[i];
        if (v > 1u) viI = 1;
        if (v != 0u && v != 0x3f800000u) viF = 1;
    }
    __syncthreads();
    if (threadIdx.x == 0) g_maskmode = (viI == 0) ? 0 : ((viF == 0) ? 1 : 2);
}

__global__ void k_convert_mask(const unsigned char* __restrict__ p) {
    int i = blockIdx.x * blockDim.x + threadIdx.x;
    if (i >= Bn * Mn) return;
    int mode = g_maskmode;
    unsigned char v;
    if (mode == 0)      v = (((const int*)p)[i]   != 0);
    else if (mode == 1) v = (((const float*)p)[i] != 0.0f);
    else                v = (p[i] != 0);
    g_maskb[i] = v;
}

// ---------------- K1: pooled = mean over S of context ----------------
__global__ void k_pool(const float* __restrict__ context) {
    int b = blockIdx.x;
    int d = threadIdx.x;                  // 512 threads
    const float* base = context + (size_t)b * Sn * Dn + d;
    float s = 0.f;
    #pragma unroll 8
    for (int i = 0; i < Sn; i++) s += base[(size_t)i * Dn];
    g_pooled[b * Dn + d] = s * (1.0f / Sn);
}

// ---------------- K2a: cvec[b,d] = pooled[b]·ctx_w[d] + ctx_b[d] ----------------
__global__ void k_cvec(const float* __restrict__ ctx_w, const float* __restrict__ ctx_b) {
    int wg = blockIdx.x * 8 + (threadIdx.x >> 5);   // 4096 warps
    int lane = threadIdx.x & 31;
    int b = wg >> 9, d = wg & 511;
    const float* pr = g_pooled + b * Dn;
    const float* wr = ctx_w + (size_t)d * Dn;
    float s = 0.f;
    for (int i = lane; i < Dn; i += 32) s += pr[i] * wr[i];
    #pragma unroll
    for (int o = 16; o > 0; o >>= 1) s += __shfl_down_sync(0xffffffffu, s, o);
    if (lane == 0) g_cvec[b * Dn + d] = s + ctx_b[d];
}

// ---------------- K2b: queries = queries_param + cvec; also write to out ----------------
__global__ void k_queries(const float* __restrict__ qp, float* __restrict__ out) {
    int idx = blockIdx.x * blockDim.x + threadIdx.x;   // 131072
    int d = idx & 511, q = (idx >> 9) & 31, b = idx >> 14;
    float v = qp[q * Dn + d] + g_cvec[b * Dn + d];
    g_queries[idx] = v;
    out[OUT_QUER + idx] = v;
}

// ---------------- K2c: gates = sigmoid(pooled·gate_w + gate_b) ----------------
__global__ void k_gates(const float* __restrict__ gate_w, const float* __restrict__ gate_b,
                        float* __restrict__ out) {
    int wg = blockIdx.x * 8 + (threadIdx.x >> 5);    // 256 warps
    int lane = threadIdx.x & 31;
    int b = wg >> 5, q = wg & 31;
    const float* pr = g_pooled + b * Dn;
    const float* wr = gate_w + (size_t)q * Dn;
    float s = 0.f;
    for (int i = lane; i < Dn; i += 32) s += pr[i] * wr[i];
    #pragma unroll
    for (int o = 16; o > 0; o >>= 1) s += __shfl_down_sync(0xffffffffu, s, o);
    if (lane == 0) {
        float x = s + gate_b[q];
        float g = 1.0f / (1.0f + __expf(-x));
        g_gates[wg] = g;
        out[OUT_GATE + wg] = g;
    }
}

// ---------------- generic fp32 NT GEMM (small GEMMs), double-buffered ----------------
// C[r][n] = sum_k A[r][k]*B[n][k] (+colBias)
// tiles: BM=128, BN=64, KT=16; 256 threads, each 8x4.
__global__ void __launch_bounds__(256)
gemm_nt(const float* __restrict__ A, int lda, long long sA,
        const float* __restrict__ Bm, int ldb, long long sB,
        float* __restrict__ C, int ldc, long long sC,
        int K,
        const float* __restrict__ colBias, long long sCB) {
    const int bn = blockIdx.x, bm = blockIdx.y, bz = blockIdx.z;
    const float* Ab = A + (size_t)bz * sA + (size_t)bm * 128 * lda;
    const float* Bb = Bm + (size_t)bz * sB + (size_t)bn * 64 * ldb;
    float* Cb = C + (size_t)bz * sC + (size_t)bm * 128 * ldc + (size_t)bn * 64;

    __shared__ float As[2][16][132];
    __shared__ float Bs[2][16][68];

    const int tid = threadIdx.x;
    const int tx = tid & 15;
    const int ty = tid >> 4;
    const int arow0 = tid >> 2, akq = tid & 3;
    const int bcol = tid >> 2, bkq = tid & 3;

    float acc[8][4];
    #pragma unroll
    for (int i = 0; i < 8; i++)
        #pragma unroll
        for (int j = 0; j < 4; j++) acc[i][j] = 0.f;

    {
        #pragma unroll
        for (int it = 0; it < 2; it++) {
            int row = arow0 + it * 64;
            float4 v = *(const float4*)(Ab + (size_t)row * lda + akq * 4);
            As[0][akq * 4 + 0][row] = v.x; As[0][akq * 4 + 1][row] = v.y;
            As[0][akq * 4 + 2][row] = v.z; As[0][akq * 4 + 3][row] = v.w;
        }
        float4 v = *(const float4*)(Bb + (size_t)bcol * ldb + bkq * 4);
        Bs[0][bkq * 4 + 0][bcol] = v.x; Bs[0][bkq * 4 + 1][bcol] = v.y;
        Bs[0][bkq * 4 + 2][bcol] = v.z; Bs[0][bkq * 4 + 3][bcol] = v.w;
    }
    __syncthreads();

    int buf = 0;
    for (int k0 = 0; k0 < K; k0 += 16) {
        const bool has_next = (k0 + 16) < K;
        float4 pa0, pa1, pb;
        if (has_next) {
            int kn = k0 + 16;
            pa0 = *(const float4*)(Ab + (size_t)(arow0)      * lda + kn + akq * 4);
            pa1 = *(const float4*)(Ab + (size_t)(arow0 + 64) * lda + kn + akq * 4);
            pb  = *(const float4*)(Bb + (size_t)bcol * ldb + kn + bkq * 4);
        }
        #pragma unroll
        for (int k = 0; k < 16; k++) {
            float a[8], b[4];
            #pragma unroll
            for (int i = 0; i < 8; i++) a[i] = As[buf][k][ty * 8 + i];
            #pragma unroll
            for (int j = 0; j < 4; j++) b[j] = Bs[buf][k][tx * 4 + j];
            #pragma unroll
            for (int i = 0; i < 8; i++)
                #pragma unroll
                for (int j = 0; j < 4; j++) acc[i][j] += a[i] * b[j];
        }
        if (has_next) {
            int nb = buf ^ 1;
            As[nb][akq * 4 + 0][arow0] = pa0.x; As[nb][akq * 4 + 1][arow0] = pa0.y;
            As[nb][akq * 4 + 2][arow0] = pa0.z; As[nb][akq * 4 + 3][arow0] = pa0.w;
            As[nb][akq * 4 + 0][arow0 + 64] = pa1.x; As[nb][akq * 4 + 1][arow0 + 64] = pa1.y;
            As[nb][akq * 4 + 2][arow0 + 64] = pa1.z; As[nb][akq * 4 + 3][arow0 + 64] = pa1.w;
            Bs[nb][bkq * 4 + 0][bcol] = pb.x; Bs[nb][bkq * 4 + 1][bcol] = pb.y;
            Bs[nb][bkq * 4 + 2][bcol] = pb.z; Bs[nb][bkq * 4 + 3][bcol] = pb.w;
            __syncthreads();
            buf = nb;
        }
    }

    #pragma unroll
    for (int i = 0; i < 8; i++) {
        int row = ty * 8 + i;
        #pragma unroll
        for (int j = 0; j < 4; j++) {
            int col = tx * 4 + j;
            float v = acc[i][j];
            if (colBias) v += colBias[bz * sCB + bn * 64 + col];
            Cb[(size_t)row * ldc + col] = v;
        }
    }
}

// ---------------- tf32 scores GEMM (3xTF32 split) ----------------
// per batch bz: scores[256][8192] = qk[256][512] @ memory[8192][512]^T + sbias, masked
// CTA tile 128x64, BK=16, 8 warps 4m x 2n (warp tile 32x32)
__global__ void __launch_bounds__(256)
gemm_tf32_scores(const float* __restrict__ memory) {
    const int bn = blockIdx.x, bm = blockIdx.y, bz = blockIdx.z;
    const float* Ab = g_qk + (size_t)bz * RROWS * Dn + (size_t)bm * 128 * Dn;
    const float* Bb = memory + (size_t)bz * Mn * Dn + (size_t)bn * 64 * Dn;
    float* Cb = g_attn + (size_t)bz * RROWS * Mn + (size_t)bm * 128 * Mn + bn * 64;

    __shared__ float As[2][16][132];   // [buf][k][m]
    __shared__ float Bs[2][16][68];    // [buf][k][n]

    const int tid = threadIdx.x;
    const int lane = tid & 31, warp = tid >> 5;
    const int wm = (warp & 3) * 32;
    const int wn = (warp >> 2) * 32;
    const int gid = lane >> 2, tig = lane & 3;

    const int arow0 = tid >> 2, akq = tid & 3;
    const int bcol = tid >> 2, bkq = tid & 3;

    float acc[2][4][4];
    #pragma unroll
    for (int mi = 0; mi < 2; mi++)
        #pragma unroll
        for (int ni = 0; ni < 4; ni++)
            #pragma unroll
            for (int j = 0; j < 4; j++) acc[mi][ni][j] = 0.f;

    {
        #pragma unroll
        for (int it = 0; it < 2; it++) {
            int row = arow0 + it * 64;
            float4 v = *(const float4*)(Ab + (size_t)row * Dn + akq * 4);
            As[0][akq * 4 + 0][row] = v.x; As[0][akq * 4 + 1][row] = v.y;
            As[0][akq * 4 + 2][row] = v.z; As[0][akq * 4 + 3][row] = v.w;
        }
        float4 v = *(const float4*)(Bb + (size_t)bcol * Dn + bkq * 4);
        Bs[0][bkq * 4 + 0][bcol] = v.x; Bs[0][bkq * 4 + 1][bcol] = v.y;
        Bs[0][bkq * 4 + 2][bcol] = v.z; Bs[0][bkq * 4 + 3][bcol] = v.w;
    }
    __syncthreads();

    int buf = 0;
    for (int k0 = 0; k0 < Dn; k0 += 16) {
        const bool has_next = (k0 + 16) < Dn;
        float4 pa0, pa1, pb;
        if (has_next) {
            int kn = k0 + 16;
            pa0 = *(const float4*)(Ab + (size_t)(arow0)      * Dn + kn + akq * 4);
            pa1 = *(const float4*)(Ab + (size_t)(arow0 + 64) * Dn + kn + akq * 4);
            pb  = *(const float4*)(Bb + (size_t)bcol * Dn + kn + bkq * 4);
        }
        #pragma unroll
        for (int kk = 0; kk < 16; kk += 8) {
            unsigned ah[2][4], al[2][4];
            #pragma unroll
            for (int mi = 0; mi < 2; mi++) {
                int m0 = wm + mi * 16;
                float x0 = As[buf][kk + tig][m0 + gid];
                float x1 = As[buf][kk + tig][m0 + gid + 8];
                float x2 = As[buf][kk + 4 + tig][m0 + gid];
                float x3 = As[buf][kk + 4 + tig][m0 + gid + 8];
                split_tf32(x0, ah[mi][0], al[mi][0]);
                split_tf32(x1, ah[mi][1], al[mi][1]);
                split_tf32(x2, ah[mi][2], al[mi][2]);
                split_tf32(x3, ah[mi][3], al[mi][3]);
            }
            unsigned bh[4][2], bl[4][2];
            #pragma unroll
            for (int ni = 0; ni < 4; ni++) {
                int n0 = wn + ni * 8;
                float y0 = Bs[buf][kk + tig][n0 + gid];
                float y1 = Bs[buf][kk + 4 + tig][n0 + gid];
                split_tf32(y0, bh[ni][0], bl[ni][0]);
                split_tf32(y1, bh[ni][1], bl[ni][1]);
            }
            #pragma unroll
            for (int mi = 0; mi < 2; mi++)
                #pragma unroll
                for (int ni = 0; ni < 4; ni++) {
                    mma_tf32(acc[mi][ni], ah[mi], bh[ni]);
                    mma_tf32(acc[mi][ni], ah[mi], bl[ni]);
                    mma_tf32(acc[mi][ni], al[mi], bh[ni]);
                }
        }
        if (has_next) {
            int nb = buf ^ 1;
            As[nb][akq * 4 + 0][arow0] = pa0.x; As[nb][akq * 4 + 1][arow0] = pa0.y;
            As[nb][akq * 4 + 2][arow0] = pa0.z; As[nb][akq * 4 + 3][arow0] = pa0.w;
            As[nb][akq * 4 + 0][arow0 + 64] = pa1.x; As[nb][akq * 4 + 1][arow0 + 64] = pa1.y;
            As[nb][akq * 4 + 2][arow0 + 64] = pa1.z; As[nb][akq * 4 + 3][arow0 + 64] = pa1.w;
            Bs[nb][bkq * 4 + 0][bcol] = pb.x; Bs[nb][bkq * 4 + 1][bcol] = pb.y;
            Bs[nb][bkq * 4 + 2][bcol] = pb.z; Bs[nb][bkq * 4 + 3][bcol] = pb.w;
            __syncthreads();
            buf = nb;
        }
    }

    const float NEGINF = __int_as_float(0xff800000);
    #pragma unroll
    for (int mi = 0; mi < 2; mi++) {
        int r0 = wm + mi * 16 + gid;
        int r1 = r0 + 8;
        float sb0 = g_sbias[bz * RROWS + bm * 128 + r0];
        float sb1 = g_sbias[bz * RROWS + bm * 128 + r1];
        #pragma unroll
        for (int ni = 0; ni < 4; ni++) {
            int cl = wn + ni * 8 + tig * 2;
            int gc = bn * 64 + cl;
            unsigned char m0v = g_maskb[bz * Mn + gc];
            unsigned char m1v = g_maskb[bz * Mn + gc + 1];
            float2 v0, v1;
            v0.x = m0v ? acc[mi][ni][0] + sb0 : NEGINF;
            v0.y = m1v ? acc[mi][ni][1] + sb0 : NEGINF;
            v1.x = m0v ? acc[mi][ni][2] + sb1 : NEGINF;
            v1.y = m1v ? acc[mi][ni][3] + sb1 : NEGINF;
            *(float2*)(Cb + (size_t)r0 * Mn + cl) = v0;
            *(float2*)(Cb + (size_t)r1 * Mn + cl) = v1;
        }
    }
}

// ---------------- tf32 AM GEMM (3xTF32 split), NN ----------------
// per batch b: AM[256][512] = attn[256][8192] @ memory[8192][512]
// CTA tile 128x32, BK=16, 8 warps 4m x 2n (warp tile 32x16); out layout [h][b][q][d]
__global__ void __launch_bounds__(256)
gemm_tf32_am(const float* __restrict__ memory) {
    const int bn = blockIdx.x, bm = blockIdx.y, b = blockIdx.z;   // bn<16
    const float* Ab = g_attn + (size_t)b * RROWS * Mn + (size_t)bm * 128 * Mn;
    const float* Bb = memory + (size_t)b * Mn * Dn + bn * 32;

    __shared__ float As[2][16][132];   // [buf][k][m]
    __shared__ float Bs[2][16][36];    // [buf][k][n]

    const int tid = threadIdx.x;
    const int lane = tid & 31, warp = tid >> 5;
    const int wm = (warp & 3) * 32;
    const int wn = (warp >> 2) * 16;
    const int gid = lane >> 2, tig = lane & 3;

    const int arow0 = tid >> 2, akq = tid & 3;
    const int bkr = tid >> 3, bcq = tid & 7;       // tid<128: 16 k-rows x 8 float4

    float acc[2][2][4];
    #pragma unroll
    for (int mi = 0; mi < 2; mi++)
        #pragma unroll
        for (int ni = 0; ni < 2; ni++)
            #pragma unroll
            for (int j = 0; j < 4; j++) acc[mi][ni][j] = 0.f;

    {
        #pragma unroll
        for (int it = 0; it < 2; it++) {
            int row = arow0 + it * 64;
            float4 v = *(const float4*)(Ab + (size_t)row * Mn + akq * 4);
            As[0][akq * 4 + 0][row] = v.x; As[0][akq * 4 + 1][row] = v.y;
            As[0][akq * 4 + 2][row] = v.z; As[0][akq * 4 + 3][row] = v.w;
        }
        if (tid < 128) {
            float4 v = *(const float4*)(Bb + (size_t)bkr * Dn + bcq * 4);
            Bs[0][bkr][bcq * 4 + 0] = v.x; Bs[0][bkr][bcq * 4 + 1] = v.y;
            Bs[0][bkr][bcq * 4 + 2] = v.z; Bs[0][bkr][bcq * 4 + 3] = v.w;
        }
    }
    __syncthreads();

    int buf = 0;
    for (int k0 = 0; k0 < Mn; k0 += 16) {
        const bool has_next = (k0 + 16) < Mn;
        float4 pa0, pa1, pb;
        if (has_next) {
            int kn = k0 + 16;
            pa0 = *(const float4*)(Ab + (size_t)(arow0)      * Mn + kn + akq * 4);
            pa1 = *(const float4*)(Ab + (size_t)(arow0 + 64) * Mn + kn + akq * 4);
            if (tid < 128) pb = *(const float4*)(Bb + (size_t)(kn + bkr) * Dn + bcq * 4);
        }
        #pragma unroll
        for (int kk = 0; kk < 16; kk += 8) {
            unsigned ah[2][4], al[2][4];
            #pragma unroll
            for (int mi = 0; mi < 2; mi++) {
                int m0 = wm + mi * 16;
                float x0 = As[buf][kk + tig][m0 + gid];
                float x1 = As[buf][kk + tig][m0 + gid + 8];
                float x2 = As[buf][kk + 4 + tig][m0 + gid];
                float x3 = As[buf][kk + 4 + tig][m0 + gid + 8];
                split_tf32(x0, ah[mi][0], al[mi][0]);
                split_tf32(x1, ah[mi][1], al[mi][1]);
                split_tf32(x2, ah[mi][2], al[mi][2]);
                split_tf32(x3, ah[mi][3], al[mi][3]);
            }
            unsigned bh[2][2], bl[2][2];
            #pragma unroll
            for (int ni = 0; ni < 2; ni++) {
                int n0 = wn + ni * 8;
                float y0 = Bs[buf][kk + tig][n0 + gid];
                float y1 = Bs[buf][kk + 4 + tig][n0 + gid];
                split_tf32(y0, bh[ni][0], bl[ni][0]);
                split_tf32(y1, bh[ni][1], bl[ni][1]);
            }
            #pragma unroll
            for (int mi = 0; mi < 2; mi++)
                #pragma unroll
                for (int ni = 0; ni < 2; ni++) {
                    mma_tf32(acc[mi][ni], ah[mi], bh[ni]);
                    mma_tf32(acc[mi][ni], ah[mi], bl[ni]);
                    mma_tf32(acc[mi][ni], al[mi], bh[ni]);
                }
        }
        if (has_next) {
            int nb = buf ^ 1;
            As[nb][akq * 4 + 0][arow0] = pa0.x; As[nb][akq * 4 + 1][arow0] = pa0.y;
            As[nb][akq * 4 + 2][arow0] = pa0.z; As[nb][akq * 4 + 3][arow0] = pa0.w;
            As[nb][akq * 4 + 0][arow0 + 64] = pa1.x; As[nb][akq * 4 + 1][arow0 + 64] = pa1.y;
            As[nb][akq * 4 + 2][arow0 + 64] = pa1.z; As[nb][akq * 4 + 3][arow0 + 64] = pa1.w;
            if (tid < 128) {
                Bs[nb][bkr][bcq * 4 + 0] = pb.x; Bs[nb][bkr][bcq * 4 + 1] = pb.y;
                Bs[nb][bkr][bcq * 4 + 2] = pb.z; Bs[nb][bkr][bcq * 4 + 3] = pb.w;
            }
            __syncthreads();
            buf = nb;
        }
    }

    #pragma unroll
    for (int mi = 0; mi < 2; mi++) {
        #pragma unroll
        for (int p = 0; p < 2; p++) {
            int rl = wm + mi * 16 + gid + p * 8;
            int r = bm * 128 + rl;
            int h = r >> 5, q = r & 31;
            float* base = g_AM + (size_t)((h * Bn + b) * Qn + q) * Dn + bn * 32;
            #pragma unroll
            for (int ni = 0; ni < 2; ni++) {
                int cl = wn + ni * 8 + tig * 2;
                float2 v;
                v.x = acc[mi][ni][p * 2 + 0];
                v.y = acc[mi][ni][p * 2 + 1];
                *(float2*)(base + cl) = v;
            }
        }
    }
}

// ---------------- K3b: fold wk into q-side: qk = scale*(qh @ wk_h); sbias = scale*qh·bk_h --
__global__ void k_fold_qk(const float* __restrict__ in_w, const float* __restrict__ in_b) {
    int b = blockIdx.x >> 3, h = blockIdx.x & 7;
    int d = threadIdx.x;                                 // 512 threads
    __shared__ float qs[Qn][HDn + 1];
    for (int l = threadIdx.x; l < Qn * HDn; l += blockDim.x) {
        int q = l >> 6, hd = l & 63;
        qs[q][hd] = g_qh[((size_t)(b * Qn + q)) * Dn + h * HDn + hd];
    }
    __syncthreads();

    float acc[Qn];
    #pragma unroll
    for (int q = 0; q < Qn; q++) acc[q] = 0.f;
    for (int hd = 0; hd < HDn; hd++) {
        float w = in_w[((size_t)(Dn + h * HDn + hd)) * Dn + d];
        #pragma unroll
        for (int q = 0; q < Qn; q++) acc[q] += qs[q][hd] * w;
    }
    float* outp = g_qk + (size_t)b * RROWS * Dn + (size_t)(h * Qn) * Dn + d;
    #pragma unroll
    for (int q = 0; q < Qn; q++) outp[(size_t)q * Dn] = SCALE * acc[q];

    if (threadIdx.x < Qn) {
        int q = threadIdx.x;
        float sb = 0.f;
        for (int hd = 0; hd < HDn; hd++) sb += qs[q][hd] * in_b[Dn + h * HDn + hd];
        g_sbias[b * RROWS + h * Qn + q] = SCALE * sb;
    }
}

// ---------------- K5: softmax over each 8192-row of g_attn (in place) ----------------
__global__ void __launch_bounds__(256) k_softmax() {
    __shared__ float buf[Mn];
    __shared__ float red[256];
    int row = blockIdx.x;
    float* base = g_attn + (size_t)row * Mn;
    int tid = threadIdx.x;

    float lmax = -INFINITY;
    for (int i = tid; i < Mn; i += 256) {
        float v = base[i];
        buf[i] = v;
        lmax = fmaxf(lmax, v);
    }
    red[tid] = lmax; __syncthreads();
    for (int s = 128; s > 0; s >>= 1) {
        if (tid < s) red[tid] = fmaxf(red[tid], red[tid + s]);
        __syncthreads();
    }
    float gmax = red[0]; __syncthreads();

    float lsum = 0.f;
    for (int i = tid; i < Mn; i += 256) {
        float e = __expf(buf[i] - gmax);
        buf[i] = e;
        lsum += e;
    }
    red[tid] = lsum; __syncthreads();
    for (int s = 128; s > 0; s >>= 1) {
        if (tid < s) red[tid] += red[tid + s];
        __syncthreads();
    }
    float inv = 1.0f / red[0];
    for (int i = tid; i < Mn; i += 256) base[i] = buf[i] * inv;
}

// ---------------- K6: attention = mean over heads (float4) ----------------
__global__ void k_attn_mean(float* __restrict__ out) {
    int gid = blockIdx.x * blockDim.x + threadIdx.x;   // 524,288 vec4 elems
    int mv = gid & 2047, q = (gid >> 11) & 31, b = gid >> 16;
    const float4* base = (const float4*)(g_attn + (size_t)b * RROWS * Mn + (size_t)q * Mn) + mv;
    float4 s = make_float4(0.f, 0.f, 0.f, 0.f);
    #pragma unroll
    for (int h = 0; h < Hn; h++) {
        float4 v = base[(size_t)h * Qn * Mn / 4];
        s.x += v.x; s.y += v.y; s.z += v.z; s.w += v.w;
    }
    s.x *= 0.125f; s.y *= 0.125f; s.z *= 0.125f; s.w *= 0.125f;
    ((float4*)(out + OUT_ATTN))[((size_t)b * Qn + q) * (Mn / 4) + mv] = s;
}

// ---------------- K10: gate multiply + layernorm ----------------
__global__ void __launch_bounds__(256) k_gate_ln(const float* __restrict__ ln_g,
                                                const float* __restrict__ ln_b,
                                                float* __restrict__ out) {
    __shared__ float rbuf[Dn];
    __shared__ float red[256];
    int row = blockIdx.x;
    int tid = threadIdx.x;
    float g = g_gates[row];
    const float* rp = g_read + (size_t)row * Dn;

    float lsum = 0.f;
    for (int i = tid; i < Dn; i += 256) {
        float v = rp[i] * g;
        rbuf[i] = v;
        lsum += v;
    }
    red[tid] = lsum; __syncthreads();
    for (int s = 128; s > 0; s >>= 1) { if (tid < s) red[tid] += red[tid + s]; __syncthreads(); }
    float mu = red[0] * (1.0f / Dn); __syncthreads();

    float lv = 0.f;
    for (int i = tid; i < Dn; i += 256) {
        float d = rbuf[i] - mu;
        lv += d * d;
    }
    red[tid] = lv; __syncthreads();
    for (int s = 128; s > 0; s >>= 1) { if (tid < s) red[tid] += red[tid + s]; __syncthreads(); }
    float inv = rsqrtf(red[0] * (1.0f / Dn) + 1e-5f);

    for (int i = tid; i < Dn; i += 256)
        out[OUT_READ + (size_t)row * Dn + i] = (rbuf[i] - mu) * inv * ln_g[i] + ln_b[i];
}

// =============================== host launcher ===============================
extern "C" void kernel_launch(void* const* d_in, const int* in_sizes, int n_in,
                              void* d_out, int out_size) {
    const float* memory  = (const float*)d_in[0];
    const float* context = (const float*)d_in[1];
    const unsigned char* mask = (const unsigned char*)d_in[2];
    const float* qp      = (const float*)d_in[3];
    const float* ctx_w   = (const float*)d_in[4];
    const float* ctx_b   = (const float*)d_in[5];
    const float* in_w    = (const float*)d_in[6];
    const float* in_b    = (const float*)d_in[7];
    const float* out_w   = (const float*)d_in[8];
    const float* out_b   = (const float*)d_in[9];
    const float* ln_g    = (const float*)d_in[10];
    const float* ln_b    = (const float*)d_in[11];
    const float* gate_w  = (const float*)d_in[12];
    const float* gate_b  = (const float*)d_in[13];
    float* out = (float*)d_out;

    static float *p_queries = nullptr, *p_qh = nullptr, *p_AM = nullptr,
                 *p_ctx = nullptr, *p_read = nullptr;
    if (!p_queries) {
        cudaGetSymbolAddress((void**)&p_queries, g_queries);
        cudaGetSymbolAddress((void**)&p_qh, g_qh);
        cudaGetSymbolAddress((void**)&p_AM, g_AM);
        cudaGetSymbolAddress((void**)&p_ctx, g_ctx);
        cudaGetSymbolAddress((void**)&p_read, g_read);
    }

    // mask dtype sniff + normalize
    k_detect<<<1, 256>>>(mask);
    k_convert_mask<<<(Bn * Mn + 255) / 256, 256>>>(mask);

    // pooled / cvec / queries / gates
    k_pool<<<Bn, Dn>>>(context);
    k_cvec<<<512, 256>>>(ctx_w, ctx_b);
    k_queries<<<Bn * Qn * Dn / 256, 256>>>(qp, out);
    k_gates<<<32, 256>>>(gate_w, gate_b, out);

    // qh = queries @ wq^T + bq   (M=256, N=512, K=512)
    gemm_nt<<<dim3(Dn / 64, 2, 1), 256>>>(
        p_queries, Dn, 0, in_w, Dn, 0, p_qh, Dn, 0, Dn, in_b, 0);

    // fold wk: qk, sbias
    k_fold_qk<<<Bn * Hn, Dn>>>(in_w, in_b);

    // scores = qk @ memory^T + sbias, masked  (tf32 tensor cores)
    gemm_tf32_scores<<<dim3(Mn / 64, 2, Bn), 256>>>(memory);

    // softmax rows
    k_softmax<<<Bn * RROWS, 256>>>();

    // attention = mean over heads -> out
    k_attn_mean<<<Bn * Qn * (Mn / 4) / 256, 256>>>(out);

    // AM = attn @ memory  (tf32 tensor cores)
    gemm_tf32_am<<<dim3(Dn / 32, 2, Bn), 256>>>(memory);

    // ctx = AM_h @ wv_h^T + bv_h  (batched over heads: 256 x 64, K=512)
    gemm_nt<<<dim3(1, 2, Hn), 256>>>(
        p_AM, Dn, (long long)Bn * Qn * Dn,
        in_w + (size_t)2 * Dn * Dn, Dn, (long long)HDn * Dn,
        p_ctx, Dn, (long long)HDn, Dn,
        in_b + 2 * Dn, HDn);

    // readouts = ctx @ out_w^T + out_b  (256 x 512, K=512)
    gemm_nt<<<dim3(Dn / 64, 2, 1), 256>>>(
        p_ctx, Dn, 0, out_w, Dn, 0, p_read, Dn, 0, Dn, out_b, 0);

    // gate + layernorm -> out
    k_gate_ln<<<Bn * Qn, 256>>>(ln_g, ln_b, out);
}

// round 8
// speedup vs baseline: 1.1545x; 1.1545x over previous
#include <cuda_runtime.h>
#include <math.h>

#define Bn   8
#define Mn   8192
#define Sn   128
#define Dn   512
#define Qn   32
#define Hn   8
#define HDn  64
#define RROWS 256          // Hn*Qn rows per batch
#define SCALE 0.125f       // 1/sqrt(64)

// ---- output section offsets (floats) ----
#define OUT_READ  0
#define OUT_ATTN  131072
#define OUT_GATE  2228224
#define OUT_QUER  2228480

// ---------------- scratch (__device__ globals; no allocation) ----------------
__device__ float g_pooled[Bn*Dn];
__device__ float g_cvec[Bn*Dn];
__device__ float g_queries[Bn*Qn*Dn];
__device__ float g_qh[Bn*Qn*Dn];
__device__ float g_qk[Bn*RROWS*Dn];
__device__ float g_sbias[Bn*RROWS];
__device__ float g_attn[(size_t)Bn*RROWS*Mn];     // 64 MB: scores -> attn
__device__ float g_AM[Hn*Bn*Qn*Dn];               // [h][b][q][d]
__device__ float g_ctx[Bn*Qn*Dn];
__device__ float g_read[Bn*Qn*Dn];
__device__ float g_gates[Bn*Qn];
__device__ unsigned char g_maskb[Bn*Mn];
__device__ int g_maskmode;

// ---------------- bf16 split helpers ----------------
// pack2: (x0, x1) -> h = {bf16(x1) : bf16(x0)}  (x0 in low half = even-k element)
//        l = packed residuals
__device__ __forceinline__ void pack2(float x0, float x1, unsigned &h, unsigned &l) {
    asm("cvt.rn.bf16x2.f32 %0, %1, %2;" : "=r"(h) : "f"(x1), "f"(x0));
    float h0 = __uint_as_float(h << 16);
    float h1 = __uint_as_float(h & 0xffff0000u);
    asm("cvt.rn.bf16x2.f32 %0, %1, %2;" : "=r"(l) : "f"(x1 - h1), "f"(x0 - h0));
}

__device__ __forceinline__ void mma_bf16(float* c, const unsigned* a, const unsigned* b) {
    asm volatile("mma.sync.aligned.m16n8k16.row.col.f32.bf16.bf16.f32 "
        "{%0,%1,%2,%3}, {%4,%5,%6,%7}, {%8,%9}, {%0,%1,%2,%3};\n"
        : "+f"(c[0]), "+f"(c[1]), "+f"(c[2]), "+f"(c[3])
        : "r"(a[0]), "r"(a[1]), "r"(a[2]), "r"(a[3]), "r"(b[0]), "r"(b[1]));
}

// ---------------- mask dtype sniffer + normalizer ----------------
__global__ void k_detect(const unsigned char* __restrict__ p) {
    __shared__ int viI, viF;
    if (threadIdx.x == 0) { viI = 0; viF = 0; }
    __syncthreads();
    const unsigned int* w = (const unsigned int*)p;
    for (int i = threadIdx.x; i < 4096; i += blockDim.x) {
        unsigned int v = w[i];
        if (v > 1u) viI = 1;
        if (v != 0u && v != 0x3f800000u) viF = 1;
    }
    __syncthreads();
    if (threadIdx.x == 0) g_maskmode = (viI == 0) ? 0 : ((viF == 0) ? 1 : 2);
}

__global__ void k_convert_mask(const unsigned char* __restrict__ p) {
    int i = blockIdx.x * blockDim.x + threadIdx.x;
    if (i >= Bn * Mn) return;
    int mode = g_maskmode;
    unsigned char v;
    if (mode == 0)      v = (((const int*)p)[i]   != 0);
    else if (mode == 1) v = (((const float*)p)[i] != 0.0f);
    else                v = (p[i] != 0);
    g_maskb[i] = v;
}

// ---------------- K1: pooled = mean over S of context (64 CTAs) ----------------
__global__ void __launch_bounds__(512) k_pool(const float* __restrict__ context) {
    int b = blockIdx.x, d0 = blockIdx.y * 64;
    int tid = threadIdx.x;
    int dl = tid & 63, sg = tid >> 6;             // 8 s-groups
    const float* base = context + (size_t)b * Sn * Dn + d0 + dl;
    float s = 0.f;
    for (int i = sg; i < Sn; i += 8) s += base[(size_t)i * Dn];
    __shared__ float red[512];
    red[tid] = s; __syncthreads();
    if (tid < 256) red[tid] += red[tid + 256];
    __syncthreads();
    if (tid < 128) red[tid] += red[tid + 128];
    __syncthreads();
    if (tid < 64) g_pooled[b * Dn + d0 + tid] = (red[tid] + red[tid + 64]) * (1.0f / Sn);
}

// ---------------- K2a: cvec[b,d] = pooled[b]·ctx_w[d] + ctx_b[d] ----------------
__global__ void k_cvec(const float* __restrict__ ctx_w, const float* __restrict__ ctx_b) {
    int wg = blockIdx.x * 8 + (threadIdx.x >> 5);   // 4096 warps
    int lane = threadIdx.x & 31;
    int b = wg >> 9, d = wg & 511;
    const float* pr = g_pooled + b * Dn;
    const float* wr = ctx_w + (size_t)d * Dn;
    float s = 0.f;
    for (int i = lane; i < Dn; i += 32) s += pr[i] * wr[i];
    #pragma unroll
    for (int o = 16; o > 0; o >>= 1) s += __shfl_down_sync(0xffffffffu, s, o);
    if (lane == 0) g_cvec[b * Dn + d] = s + ctx_b[d];
}

// ---------------- K2b: queries = queries_param + cvec; also write to out ----------------
__global__ void k_queries(const float* __restrict__ qp, float* __restrict__ out) {
    int idx = blockIdx.x * blockDim.x + threadIdx.x;   // 131072
    int d = idx & 511, q = (idx >> 9) & 31, b = idx >> 14;
    float v = qp[q * Dn + d] + g_cvec[b * Dn + d];
    g_queries[idx] = v;
    out[OUT_QUER + idx] = v;
}

// ---------------- K2c: gates = sigmoid(pooled·gate_w + gate_b) ----------------
__global__ void k_gates(const float* __restrict__ gate_w, const float* __restrict__ gate_b,
                        float* __restrict__ out) {
    int wg = blockIdx.x * 8 + (threadIdx.x >> 5);    // 256 warps
    int lane = threadIdx.x & 31;
    int b = wg >> 5, q = wg & 31;
    const float* pr = g_pooled + b * Dn;
    const float* wr = gate_w + (size_t)q * Dn;
    float s = 0.f;
    for (int i = lane; i < Dn; i += 32) s += pr[i] * wr[i];
    #pragma unroll
    for (int o = 16; o > 0; o >>= 1) s += __shfl_down_sync(0xffffffffu, s, o);
    if (lane == 0) {
        float x = s + gate_b[q];
        float g = 1.0f / (1.0f + __expf(-x));
        g_gates[wg] = g;
        out[OUT_GATE + wg] = g;
    }
}

// ---------------- generic fp32 NT GEMM (small GEMMs), double-buffered ----------------
__global__ void __launch_bounds__(256)
gemm_nt(const float* __restrict__ A, int lda, long long sA,
        const float* __restrict__ Bm, int ldb, long long sB,
        float* __restrict__ C, int ldc, long long sC,
        int K,
        const float* __restrict__ colBias, long long sCB) {
    const int bn = blockIdx.x, bm = blockIdx.y, bz = blockIdx.z;
    const float* Ab = A + (size_t)bz * sA + (size_t)bm * 128 * lda;
    const float* Bb = Bm + (size_t)bz * sB + (size_t)bn * 64 * ldb;
    float* Cb = C + (size_t)bz * sC + (size_t)bm * 128 * ldc + (size_t)bn * 64;

    __shared__ float As[2][16][132];
    __shared__ float Bs[2][16][68];

    const int tid = threadIdx.x;
    const int tx = tid & 15;
    const int ty = tid >> 4;
    const int arow0 = tid >> 2, akq = tid & 3;
    const int bcol = tid >> 2, bkq = tid & 3;

    float acc[8][4];
    #pragma unroll
    for (int i = 0; i < 8; i++)
        #pragma unroll
        for (int j = 0; j < 4; j++) acc[i][j] = 0.f;

    {
        #pragma unroll
        for (int it = 0; it < 2; it++) {
            int row = arow0 + it * 64;
            float4 v = *(const float4*)(Ab + (size_t)row * lda + akq * 4);
            As[0][akq * 4 + 0][row] = v.x; As[0][akq * 4 + 1][row] = v.y;
            As[0][akq * 4 + 2][row] = v.z; As[0][akq * 4 + 3][row] = v.w;
        }
        float4 v = *(const float4*)(Bb + (size_t)bcol * ldb + bkq * 4);
        Bs[0][bkq * 4 + 0][bcol] = v.x; Bs[0][bkq * 4 + 1][bcol] = v.y;
        Bs[0][bkq * 4 + 2][bcol] = v.z; Bs[0][bkq * 4 + 3][bcol] = v.w;
    }
    __syncthreads();

    int buf = 0;
    for (int k0 = 0; k0 < K; k0 += 16) {
        const bool has_next = (k0 + 16) < K;
        float4 pa0, pa1, pb;
        if (has_next) {
            int kn = k0 + 16;
            pa0 = *(const float4*)(Ab + (size_t)(arow0)      * lda + kn + akq * 4);
            pa1 = *(const float4*)(Ab + (size_t)(arow0 + 64) * lda + kn + akq * 4);
            pb  = *(const float4*)(Bb + (size_t)bcol * ldb + kn + bkq * 4);
        }
        #pragma unroll
        for (int k = 0; k < 16; k++) {
            float a[8], b[4];
            #pragma unroll
            for (int i = 0; i < 8; i++) a[i] = As[buf][k][ty * 8 + i];
            #pragma unroll
            for (int j = 0; j < 4; j++) b[j] = Bs[buf][k][tx * 4 + j];
            #pragma unroll
            for (int i = 0; i < 8; i++)
                #pragma unroll
                for (int j = 0; j < 4; j++) acc[i][j] += a[i] * b[j];
        }
        if (has_next) {
            int nb = buf ^ 1;
            As[nb][akq * 4 + 0][arow0] = pa0.x; As[nb][akq * 4 + 1][arow0] = pa0.y;
            As[nb][akq * 4 + 2][arow0] = pa0.z; As[nb][akq * 4 + 3][arow0] = pa0.w;
            As[nb][akq * 4 + 0][arow0 + 64] = pa1.x; As[nb][akq * 4 + 1][arow0 + 64] = pa1.y;
            As[nb][akq * 4 + 2][arow0 + 64] = pa1.z; As[nb][akq * 4 + 3][arow0 + 64] = pa1.w;
            Bs[nb][bkq * 4 + 0][bcol] = pb.x; Bs[nb][bkq * 4 + 1][bcol] = pb.y;
            Bs[nb][bkq * 4 + 2][bcol] = pb.z; Bs[nb][bkq * 4 + 3][bcol] = pb.w;
            __syncthreads();
            buf = nb;
        }
    }

    #pragma unroll
    for (int i = 0; i < 8; i++) {
        int row = ty * 8 + i;
        #pragma unroll
        for (int j = 0; j < 4; j++) {
            int col = tx * 4 + j;
            float v = acc[i][j];
            if (colBias) v += colBias[bz * sCB + bn * 64 + col];
            Cb[(size_t)row * ldc + col] = v;
        }
    }
}

// ---------------- bf16x3 scores GEMM (m16n8k16) ----------------
// per batch bz: scores[256][8192] = qk[256][512] @ memory[8192][512]^T + sbias, masked
// CTA tile 128x64, BK=16, 8 warps 4m x 2n (warp tile 32x32)
// smem: k-paired bf16x2 hi/lo planes, [kpair][m]
__global__ void __launch_bounds__(256)
gemm_bf16_scores(const float* __restrict__ memory) {
    const int bn = blockIdx.x, bm = blockIdx.y, bz = blockIdx.z;
    const float* Ab = g_qk + (size_t)bz * RROWS * Dn + (size_t)bm * 128 * Dn;
    const float* Bb = memory + (size_t)bz * Mn * Dn + (size_t)bn * 64 * Dn;
    float* Cb = g_attn + (size_t)bz * RROWS * Mn + (size_t)bm * 128 * Mn + bn * 64;

    __shared__ unsigned AsH[2][8][132], AsL[2][8][132];   // [buf][kpair][m]
    __shared__ unsigned BsH[2][8][68],  BsL[2][8][68];    // [buf][kpair][n]

    const int tid = threadIdx.x;
    const int lane = tid & 31, warp = tid >> 5;
    const int wm = (warp & 3) * 32;
    const int wn = (warp >> 2) * 32;
    const int gid = lane >> 2, tig = lane & 3;

    const int arow0 = tid >> 2, akq = tid & 3;    // A: rows arow0, arow0+64; k-quad akq
    const int bcol = tid >> 2, bkq = tid & 3;

    float acc[2][4][4];
    #pragma unroll
    for (int mi = 0; mi < 2; mi++)
        #pragma unroll
        for (int ni = 0; ni < 4; ni++)
            #pragma unroll
            for (int j = 0; j < 4; j++) acc[mi][ni][j] = 0.f;

    // initial tile -> buf 0
    {
        #pragma unroll
        for (int it = 0; it < 2; it++) {
            int row = arow0 + it * 64;
            float4 v = *(const float4*)(Ab + (size_t)row * Dn + akq * 4);
            unsigned h, l;
            pack2(v.x, v.y, h, l); AsH[0][akq * 2 + 0][row] = h; AsL[0][akq * 2 + 0][row] = l;
            pack2(v.z, v.w, h, l); AsH[0][akq * 2 + 1][row] = h; AsL[0][akq * 2 + 1][row] = l;
        }
        float4 v = *(const float4*)(Bb + (size_t)bcol * Dn + bkq * 4);
        unsigned h, l;
        pack2(v.x, v.y, h, l); BsH[0][bkq * 2 + 0][bcol] = h; BsL[0][bkq * 2 + 0][bcol] = l;
        pack2(v.z, v.w, h, l); BsH[0][bkq * 2 + 1][bcol] = h; BsL[0][bkq * 2 + 1][bcol] = l;
    }
    __syncthreads();

    int buf = 0;
    for (int k0 = 0; k0 < Dn; k0 += 16) {
        const bool has_next = (k0 + 16) < Dn;
        float4 pa0, pa1, pb;
        if (has_next) {
            int kn = k0 + 16;
            pa0 = *(const float4*)(Ab + (size_t)(arow0)      * Dn + kn + akq * 4);
            pa1 = *(const float4*)(Ab + (size_t)(arow0 + 64) * Dn + kn + akq * 4);
            pb  = *(const float4*)(Bb + (size_t)bcol * Dn + kn + bkq * 4);
        }

        // one m16n8k16 step covers the full BK=16 (kpairs 0..7)
        unsigned ah[2][4], al[2][4];
        #pragma unroll
        for (int mi = 0; mi < 2; mi++) {
            int m0 = wm + mi * 16;
            ah[mi][0] = AsH[buf][tig][m0 + gid];     ah[mi][1] = AsH[buf][tig][m0 + gid + 8];
            ah[mi][2] = AsH[buf][tig + 4][m0 + gid]; ah[mi][3] = AsH[buf][tig + 4][m0 + gid + 8];
            al[mi][0] = AsL[buf][tig][m0 + gid];     al[mi][1] = AsL[buf][tig][m0 + gid + 8];
            al[mi][2] = AsL[buf][tig + 4][m0 + gid]; al[mi][3] = AsL[buf][tig + 4][m0 + gid + 8];
        }
        unsigned bh[4][2], bl[4][2];
        #pragma unroll
        for (int ni = 0; ni < 4; ni++) {
            int n0 = wn + ni * 8;
            bh[ni][0] = BsH[buf][tig][n0 + gid]; bh[ni][1] = BsH[buf][tig + 4][n0 + gid];
            bl[ni][0] = BsL[buf][tig][n0 + gid]; bl[ni][1] = BsL[buf][tig + 4][n0 + gid];
        }
        #pragma unroll
        for (int mi = 0; mi < 2; mi++)
            #pragma unroll
            for (int ni = 0; ni < 4; ni++) {
                mma_bf16(acc[mi][ni], ah[mi], bh[ni]);
                mma_bf16(acc[mi][ni], ah[mi], bl[ni]);
                mma_bf16(acc[mi][ni], al[mi], bh[ni]);
            }

        if (has_next) {
            int nb = buf ^ 1;
            unsigned h, l;
            pack2(pa0.x, pa0.y, h, l); AsH[nb][akq * 2 + 0][arow0] = h; AsL[nb][akq * 2 + 0][arow0] = l;
            pack2(pa0.z, pa0.w, h, l); AsH[nb][akq * 2 + 1][arow0] = h; AsL[nb][akq * 2 + 1][arow0] = l;
            pack2(pa1.x, pa1.y, h, l); AsH[nb][akq * 2 + 0][arow0 + 64] = h; AsL[nb][akq * 2 + 0][arow0 + 64] = l;
            pack2(pa1.z, pa1.w, h, l); AsH[nb][akq * 2 + 1][arow0 + 64] = h; AsL[nb][akq * 2 + 1][arow0 + 64] = l;
            pack2(pb.x, pb.y, h, l);   BsH[nb][bkq * 2 + 0][bcol] = h; BsL[nb][bkq * 2 + 0][bcol] = l;
            pack2(pb.z, pb.w, h, l);   BsH[nb][bkq * 2 + 1][bcol] = h; BsL[nb][bkq * 2 + 1][bcol] = l;
            __syncthreads();
            buf = nb;
        }
    }

    const float NEGINF = __int_as_float(0xff800000);
    #pragma unroll
    for (int mi = 0; mi < 2; mi++) {
        int r0 = wm + mi * 16 + gid;
        int r1 = r0 + 8;
        float sb0 = g_sbias[bz * RROWS + bm * 128 + r0];
        float sb1 = g_sbias[bz * RROWS + bm * 128 + r1];
        #pragma unroll
        for (int ni = 0; ni < 4; ni++) {
            int cl = wn + ni * 8 + tig * 2;
            int gc = bn * 64 + cl;
            unsigned char m0v = g_maskb[bz * Mn + gc];
            unsigned char m1v = g_maskb[bz * Mn + gc + 1];
            float2 v0, v1;
            v0.x = m0v ? acc[mi][ni][0] + sb0 : NEGINF;
            v0.y = m1v ? acc[mi][ni][1] + sb0 : NEGINF;
            v1.x = m0v ? acc[mi][ni][2] + sb1 : NEGINF;
            v1.y = m1v ? acc[mi][ni][3] + sb1 : NEGINF;
            *(float2*)(Cb + (size_t)r0 * Mn + cl) = v0;
            *(float2*)(Cb + (size_t)r1 * Mn + cl) = v1;
        }
    }
}

// ---------------- bf16x3 AM GEMM (m16n8k16), NN ----------------
// per batch b: AM[256][512] = attn[256][8192] @ memory[8192][512]
// CTA tile 128x32, BK=16, 8 warps 4m x 2n (warp tile 32x16); out layout [h][b][q][d]
__global__ void __launch_bounds__(256)
gemm_bf16_am(const float* __restrict__ memory) {
    const int bn = blockIdx.x, bm = blockIdx.y, b = blockIdx.z;   // bn<16
    const float* Ab = g_attn + (size_t)b * RROWS * Mn + (size_t)bm * 128 * Mn;
    const float* Bb = memory + (size_t)b * Mn * Dn + bn * 32;

    __shared__ unsigned AsH[2][8][132], AsL[2][8][132];   // [buf][kpair][m]
    __shared__ unsigned BsH[2][8][36],  BsL[2][8][36];    // [buf][kpair][n]

    const int tid = threadIdx.x;
    const int lane = tid & 31, warp = tid >> 5;
    const int wm = (warp & 3) * 32;
    const int wn = (warp >> 2) * 16;
    const int gid = lane >> 2, tig = lane & 3;

    const int arow0 = tid >> 2, akq = tid & 3;
    const int bkp = tid >> 3, bnq = tid & 7;      // tid<64: kpair 0..7, n-quad 0..7

    float acc[2][2][4];
    #pragma unroll
    for (int mi = 0; mi < 2; mi++)
        #pragma unroll
        for (int ni = 0; ni < 2; ni++)
            #pragma unroll
            for (int j = 0; j < 4; j++) acc[mi][ni][j] = 0.f;

    {
        #pragma unroll
        for (int it = 0; it < 2; it++) {
            int row = arow0 + it * 64;
            float4 v = *(const float4*)(Ab + (size_t)row * Mn + akq * 4);
            unsigned h, l;
            pack2(v.x, v.y, h, l); AsH[0][akq * 2 + 0][row] = h; AsL[0][akq * 2 + 0][row] = l;
            pack2(v.z, v.w, h, l); AsH[0][akq * 2 + 1][row] = h; AsL[0][akq * 2 + 1][row] = l;
        }
        if (tid < 64) {
            float4 v0 = *(const float4*)(Bb + (size_t)(2 * bkp)     * Dn + bnq * 4);
            float4 v1 = *(const float4*)(Bb + (size_t)(2 * bkp + 1) * Dn + bnq * 4);
            unsigned h, l;
            pack2(v0.x, v1.x, h, l); BsH[0][bkp][bnq * 4 + 0] = h; BsL[0][bkp][bnq * 4 + 0] = l;
            pack2(v0.y, v1.y, h, l); BsH[0][bkp][bnq * 4 + 1] = h; BsL[0][bkp][bnq * 4 + 1] = l;
            pack2(v0.z, v1.z, h, l); BsH[0][bkp][bnq * 4 + 2] = h; BsL[0][bkp][bnq * 4 + 2] = l;
            pack2(v0.w, v1.w, h, l); BsH[0][bkp][bnq * 4 + 3] = h; BsL[0][bkp][bnq * 4 + 3] = l;
        }
    }
    __syncthreads();

    int buf = 0;
    for (int k0 = 0; k0 < Mn; k0 += 16) {
        const bool has_next = (k0 + 16) < Mn;
        float4 pa0, pa1, pb0, pb1;
        if (has_next) {
            int kn = k0 + 16;
            pa0 = *(const float4*)(Ab + (size_t)(arow0)      * Mn + kn + akq * 4);
            pa1 = *(const float4*)(Ab + (size_t)(arow0 + 64) * Mn + kn + akq * 4);
            if (tid < 64) {
                pb0 = *(const float4*)(Bb + (size_t)(kn + 2 * bkp)     * Dn + bnq * 4);
                pb1 = *(const float4*)(Bb + (size_t)(kn + 2 * bkp + 1) * Dn + bnq * 4);
            }
        }

        unsigned ah[2][4], al[2][4];
        #pragma unroll
        for (int mi = 0; mi < 2; mi++) {
            int m0 = wm + mi * 16;
            ah[mi][0] = AsH[buf][tig][m0 + gid];     ah[mi][1] = AsH[buf][tig][m0 + gid + 8];
            ah[mi][2] = AsH[buf][tig + 4][m0 + gid]; ah[mi][3] = AsH[buf][tig + 4][m0 + gid + 8];
            al[mi][0] = AsL[buf][tig][m0 + gid];     al[mi][1] = AsL[buf][tig][m0 + gid + 8];
            al[mi][2] = AsL[buf][tig + 4][m0 + gid]; al[mi][3] = AsL[buf][tig + 4][m0 + gid + 8];
        }
        unsigned bh[2][2], bl[2][2];
        #pragma unroll
        for (int ni = 0; ni < 2; ni++) {
            int n0 = wn + ni * 8;
            bh[ni][0] = BsH[buf][tig][n0 + gid]; bh[ni][1] = BsH[buf][tig + 4][n0 + gid];
            bl[ni][0] = BsL[buf][tig][n0 + gid]; bl[ni][1] = BsL[buf][tig + 4][n0 + gid];
        }
        #pragma unroll
        for (int mi = 0; mi < 2; mi++)
            #pragma unroll
            for (int ni = 0; ni < 2; ni++) {
                mma_bf16(acc[mi][ni], ah[mi], bh[ni]);
                mma_bf16(acc[mi][ni], ah[mi], bl[ni]);
                mma_bf16(acc[mi][ni], al[mi], bh[ni]);
            }

        if (has_next) {
            int nb = buf ^ 1;
            unsigned h, l;
            pack2(pa0.x, pa0.y, h, l); AsH[nb][akq * 2 + 0][arow0] = h; AsL[nb][akq * 2 + 0][arow0] = l;
            pack2(pa0.z, pa0.w, h, l); AsH[nb][akq * 2 + 1][arow0] = h; AsL[nb][akq * 2 + 1][arow0] = l;
            pack2(pa1.x, pa1.y, h, l); AsH[nb][akq * 2 + 0][arow0 + 64] = h; AsL[nb][akq * 2 + 0][arow0 + 64] = l;
            pack2(pa1.z, pa1.w, h, l); AsH[nb][akq * 2 + 1][arow0 + 64] = h; AsL[nb][akq * 2 + 1][arow0 + 64] = l;
            if (tid < 64) {
                pack2(pb0.x, pb1.x, h, l); BsH[nb][bkp][bnq * 4 + 0] = h; BsL[nb][bkp][bnq * 4 + 0] = l;
                pack2(pb0.y, pb1.y, h, l); BsH[nb][bkp][bnq * 4 + 1] = h; BsL[nb][bkp][bnq * 4 + 1] = l;
                pack2(pb0.z, pb1.z, h, l); BsH[nb][bkp][bnq * 4 + 2] = h; BsL[nb][bkp][bnq * 4 + 2] = l;
                pack2(pb0.w, pb1.w, h, l); BsH[nb][bkp][bnq * 4 + 3] = h; BsL[nb][bkp][bnq * 4 + 3] = l;
            }
            __syncthreads();
            buf = nb;
        }
    }

    #pragma unroll
    for (int mi = 0; mi < 2; mi++) {
        #pragma unroll
        for (int p = 0; p < 2; p++) {
            int rl = wm + mi * 16 + gid + p * 8;
            int r = bm * 128 + rl;
            int h = r >> 5, q = r & 31;
            float* base = g_AM + (size_t)((h * Bn + b) * Qn + q) * Dn + bn * 32;
            #pragma unroll
            for (int ni = 0; ni < 2; ni++) {
                int cl = wn + ni * 8 + tig * 2;
                float2 v;
                v.x = acc[mi][ni][p * 2 + 0];
                v.y = acc[mi][ni][p * 2 + 1];
                *(float2*)(base + cl) = v;
            }
        }
    }
}

// ---------------- K3b: fold wk into q-side: qk = scale*(qh @ wk_h); sbias = scale*qh·bk_h --
__global__ void k_fold_qk(const float* __restrict__ in_w, const float* __restrict__ in_b) {
    int b = blockIdx.x >> 3, h = blockIdx.x & 7;
    int d = threadIdx.x;                                 // 512 threads
    __shared__ float qs[Qn][HDn + 1];
    for (int l = threadIdx.x; l < Qn * HDn; l += blockDim.x) {
        int q = l >> 6, hd = l & 63;
        qs[q][hd] = g_qh[((size_t)(b * Qn + q)) * Dn + h * HDn + hd];
    }
    __syncthreads();

    float acc[Qn];
    #pragma unroll
    for (int q = 0; q < Qn; q++) acc[q] = 0.f;
    for (int hd = 0; hd < HDn; hd++) {
        float w = in_w[((size_t)(Dn + h * HDn + hd)) * Dn + d];
        #pragma unroll
        for (int q = 0; q < Qn; q++) acc[q] += qs[q][hd] * w;
    }
    float* outp = g_qk + (size_t)b * RROWS * Dn + (size_t)(h * Qn) * Dn + d;
    #pragma unroll
    for (int q = 0; q < Qn; q++) outp[(size_t)q * Dn] = SCALE * acc[q];

    if (threadIdx.x < Qn) {
        int q = threadIdx.x;
        float sb = 0.f;
        for (int hd = 0; hd < HDn; hd++) sb += qs[q][hd] * in_b[Dn + h * HDn + hd];
        g_sbias[b * RROWS + h * Qn + q] = SCALE * sb;
    }
}

// ---------------- K5: softmax over each 8192-row of g_attn (in place) ----------------
__global__ void __launch_bounds__(256) k_softmax() {
    __shared__ float buf[Mn];
    __shared__ float red[256];
    int row = blockIdx.x;
    float* base = g_attn + (size_t)row * Mn;
    int tid = threadIdx.x;

    float lmax = -INFINITY;
    for (int i = tid; i < Mn; i += 256) {
        float v = base[i];
        buf[i] = v;
        lmax = fmaxf(lmax, v);
    }
    red[tid] = lmax; __syncthreads();
    for (int s = 128; s > 0; s >>= 1) {
        if (tid < s) red[tid] = fmaxf(red[tid], red[tid + s]);
        __syncthreads();
    }
    float gmax = red[0]; __syncthreads();

    float lsum = 0.f;
    for (int i = tid; i < Mn; i += 256) {
        float e = __expf(buf[i] - gmax);
        buf[i] = e;
        lsum += e;
    }
    red[tid] = lsum; __syncthreads();
    for (int s = 128; s > 0; s >>= 1) {
        if (tid < s) red[tid] += red[tid + s];
        __syncthreads();
    }
    float inv = 1.0f / red[0];
    for (int i = tid; i < Mn; i += 256) base[i] = buf[i] * inv;
}

// ---------------- K6: attention = mean over heads (float4) ----------------
__global__ void k_attn_mean(float* __restrict__ out) {
    int gid = blockIdx.x * blockDim.x + threadIdx.x;   // 524,288 vec4 elems
    int mv = gid & 2047, q = (gid >> 11) & 31, b = gid >> 16;
    const float4* base = (const float4*)(g_attn + (size_t)b * RROWS * Mn + (size_t)q * Mn) + mv;
    float4 s = make_float4(0.f, 0.f, 0.f, 0.f);
    #pragma unroll
    for (int h = 0; h < Hn; h++) {
        float4 v = base[(size_t)h * Qn * Mn / 4];
        s.x += v.x; s.y += v.y; s.z += v.z; s.w += v.w;
    }
    s.x *= 0.125f; s.y *= 0.125f; s.z *= 0.125f; s.w *= 0.125f;
    ((float4*)(out + OUT_ATTN))[((size_t)b * Qn + q) * (Mn / 4) + mv] = s;
}

// ---------------- K10: gate multiply + layernorm ----------------
__global__ void __launch_bounds__(256) k_gate_ln(const float* __restrict__ ln_g,
                                                const float* __restrict__ ln_b,
                                                float* __restrict__ out) {
    __shared__ float rbuf[Dn];
    __shared__ float red[256];
    int row = blockIdx.x;
    int tid = threadIdx.x;
    float g = g_gates[row];
    const float* rp = g_read + (size_t)row * Dn;

    float lsum = 0.f;
    for (int i = tid; i < Dn; i += 256) {
        float v = rp[i] * g;
        rbuf[i] = v;
        lsum += v;
    }
    red[tid] = lsum; __syncthreads();
    for (int s = 128; s > 0; s >>= 1) { if (tid < s) red[tid] += red[tid + s]; __syncthreads(); }
    float mu = red[0] * (1.0f / Dn); __syncthreads();

    float lv = 0.f;
    for (int i = tid; i < Dn; i += 256) {
        float d = rbuf[i] - mu;
        lv += d * d;
    }
    red[tid] = lv; __syncthreads();
    for (int s = 128; s > 0; s >>= 1) { if (tid < s) red[tid] += red[tid + s]; __syncthreads(); }
    float inv = rsqrtf(red[0] * (1.0f / Dn) + 1e-5f);

    for (int i = tid; i < Dn; i += 256)
        out[OUT_READ + (size_t)row * Dn + i] = (rbuf[i] - mu) * inv * ln_g[i] + ln_b[i];
}

// =============================== host launcher ===============================
extern "C" void kernel_launch(void* const* d_in, const int* in_sizes, int n_in,
                              void* d_out, int out_size) {
    const float* memory  = (const float*)d_in[0];
    const float* context = (const float*)d_in[1];
    const unsigned char* mask = (const unsigned char*)d_in[2];
    const float* qp      = (const float*)d_in[3];
    const float* ctx_w   = (const float*)d_in[4];
    const float* ctx_b   = (const float*)d_in[5];
    const float* in_w    = (const float*)d_in[6];
    const float* in_b    = (const float*)d_in[7];
    const float* out_w   = (const float*)d_in[8];
    const float* out_b   = (const float*)d_in[9];
    const float* ln_g    = (const float*)d_in[10];
    const float* ln_b    = (const float*)d_in[11];
    const float* gate_w  = (const float*)d_in[12];
    const float* gate_b  = (const float*)d_in[13];
    float* out = (float*)d_out;

    static float *p_queries = nullptr, *p_qh = nullptr, *p_AM = nullptr,
                 *p_ctx = nullptr, *p_read = nullptr;
    if (!p_queries) {
        cudaGetSymbolAddress((void**)&p_queries, g_queries);
        cudaGetSymbolAddress((void**)&p_qh, g_qh);
        cudaGetSymbolAddress((void**)&p_AM, g_AM);
        cudaGetSymbolAddress((void**)&p_ctx, g_ctx);
        cudaGetSymbolAddress((void**)&p_read, g_read);
    }

    // mask dtype sniff + normalize
    k_detect<<<1, 256>>>(mask);
    k_convert_mask<<<(Bn * Mn + 255) / 256, 256>>>(mask);

    // pooled / cvec / queries / gates
    k_pool<<<dim3(Bn, 8), 512>>>(context);
    k_cvec<<<512, 256>>>(ctx_w, ctx_b);
    k_queries<<<Bn * Qn * Dn / 256, 256>>>(qp, out);
    k_gates<<<32, 256>>>(gate_w, gate_b, out);

    // qh = queries @ wq^T + bq   (M=256, N=512, K=512)
    gemm_nt<<<dim3(Dn / 64, 2, 1), 256>>>(
        p_queries, Dn, 0, in_w, Dn, 0, p_qh, Dn, 0, Dn, in_b, 0);

    // fold wk: qk, sbias
    k_fold_qk<<<Bn * Hn, Dn>>>(in_w, in_b);

    // scores = qk @ memory^T + sbias, masked  (bf16x3 tensor cores)
    gemm_bf16_scores<<<dim3(Mn / 64, 2, Bn), 256>>>(memory);

    // softmax rows
    k_softmax<<<Bn * RROWS, 256>>>();

    // attention = mean over heads -> out
    k_attn_mean<<<Bn * Qn * (Mn / 4) / 256, 256>>>(out);

    // AM = attn @ memory  (bf16x3 tensor cores)
    gemm_bf16_am<<<dim3(Dn / 32, 2, Bn), 256>>>(memory);

    // ctx = AM_h @ wv_h^T + bv_h  (batched over heads: 256 x 64, K=512)
    gemm_nt<<<dim3(1, 2, Hn), 256>>>(
        p_AM, Dn, (long long)Bn * Qn * Dn,
        in_w + (size_t)2 * Dn * Dn, Dn, (long long)HDn * Dn,
        p_ctx, Dn, (long long)HDn, Dn,
        in_b + 2 * Dn, HDn);

    // readouts = ctx @ out_w^T + out_b  (256 x 512, K=512)
    gemm_nt<<<dim3(Dn / 64, 2, 1), 256>>>(
        p_ctx, Dn, 0, out_w, Dn, 0, p_read, Dn, 0, Dn, out_b, 0);

    // gate + layernorm -> out
    k_gate_ln<<<Bn * Qn, 256>>>(ln_g, ln_b, out);
}

// round 9
// speedup vs baseline: 1.1997x; 1.0392x over previous
#include <cuda_runtime.h>
#include <math.h>

#define Bn   8
#define Mn   8192
#define Sn   128
#define Dn   512
#define Qn   32
#define Hn   8
#define HDn  64
#define RROWS 256          // Hn*Qn rows per batch
#define SCALE 0.125f       // 1/sqrt(64)

// ---- output section offsets (floats) ----
#define OUT_READ  0
#define OUT_ATTN  131072
#define OUT_GATE  2228224
#define OUT_QUER  2228480

// padded smem pitches: pitch mod 32 == 8 -> fragment-load bank = 8*tig+gid (conflict-free)
#define PADA 136
#define PADB 72

// ---------------- scratch (__device__ globals; no allocation) ----------------
__device__ float g_pooled[Bn*Dn];
__device__ float g_cvec[Bn*Dn];
__device__ float g_queries[Bn*Qn*Dn];
__device__ float g_qh[Bn*Qn*Dn];
__device__ float g_qk[Bn*RROWS*Dn];
__device__ float g_sbias[Bn*RROWS];
__device__ float g_attn[(size_t)Bn*RROWS*Mn];     // 64 MB: scores -> attn
__device__ float g_AM[Hn*Bn*Qn*Dn];               // [h][b][q][d]
__device__ float g_ctx[Bn*Qn*Dn];
__device__ float g_read[Bn*Qn*Dn];
__device__ float g_gates[Bn*Qn];
__device__ unsigned char g_maskb[Bn*Mn];
__device__ int g_maskmode;

// ---------------- bf16 split helpers ----------------
__device__ __forceinline__ void pack2(float x0, float x1, unsigned &h, unsigned &l) {
    asm("cvt.rn.bf16x2.f32 %0, %1, %2;" : "=r"(h) : "f"(x1), "f"(x0));
    float h0 = __uint_as_float(h << 16);
    float h1 = __uint_as_float(h & 0xffff0000u);
    asm("cvt.rn.bf16x2.f32 %0, %1, %2;" : "=r"(l) : "f"(x1 - h1), "f"(x0 - h0));
}

__device__ __forceinline__ void mma_bf16(float* c, const unsigned* a, const unsigned* b) {
    asm volatile("mma.sync.aligned.m16n8k16.row.col.f32.bf16.bf16.f32 "
        "{%0,%1,%2,%3}, {%4,%5,%6,%7}, {%8,%9}, {%0,%1,%2,%3};\n"
        : "+f"(c[0]), "+f"(c[1]), "+f"(c[2]), "+f"(c[3])
        : "r"(a[0]), "r"(a[1]), "r"(a[2]), "r"(a[3]), "r"(b[0]), "r"(b[1]));
}

// ---------------- mask dtype sniffer + normalizer ----------------
__global__ void k_detect(const unsigned char* __restrict__ p) {
    __shared__ int viI, viF;
    if (threadIdx.x == 0) { viI = 0; viF = 0; }
    __syncthreads();
    const unsigned int* w = (const unsigned int*)p;
    for (int i = threadIdx.x; i < 4096; i += blockDim.x) {
        unsigned int v = w[i];
        if (v > 1u) viI = 1;
        if (v != 0u && v != 0x3f800000u) viF = 1;
    }
    __syncthreads();
    if (threadIdx.x == 0) g_maskmode = (viI == 0) ? 0 : ((viF == 0) ? 1 : 2);
}

__global__ void k_convert_mask(const unsigned char* __restrict__ p) {
    int i = blockIdx.x * blockDim.x + threadIdx.x;
    if (i >= Bn * Mn) return;
    int mode = g_maskmode;
    unsigned char v;
    if (mode == 0)      v = (((const int*)p)[i]   != 0);
    else if (mode == 1) v = (((const float*)p)[i] != 0.0f);
    else                v = (p[i] != 0);
    g_maskb[i] = v;
}

// ---------------- K1: pooled = mean over S of context ----------------
__global__ void __launch_bounds__(512) k_pool(const float* __restrict__ context) {
    int b = blockIdx.x, d0 = blockIdx.y * 64;
    int tid = threadIdx.x;
    int dl = tid & 63, sg = tid >> 6;
    const float* base = context + (size_t)b * Sn * Dn + d0 + dl;
    float s = 0.f;
    for (int i = sg; i < Sn; i += 8) s += base[(size_t)i * Dn];
    __shared__ float red[512];
    red[tid] = s; __syncthreads();
    if (tid < 256) red[tid] += red[tid + 256];
    __syncthreads();
    if (tid < 128) red[tid] += red[tid + 128];
    __syncthreads();
    if (tid < 64) g_pooled[b * Dn + d0 + tid] = (red[tid] + red[tid + 64]) * (1.0f / Sn);
}

// ---------------- K2a: cvec ----------------
__global__ void k_cvec(const float* __restrict__ ctx_w, const float* __restrict__ ctx_b) {
    int wg = blockIdx.x * 8 + (threadIdx.x >> 5);
    int lane = threadIdx.x & 31;
    int b = wg >> 9, d = wg & 511;
    const float* pr = g_pooled + b * Dn;
    const float* wr = ctx_w + (size_t)d * Dn;
    float s = 0.f;
    for (int i = lane; i < Dn; i += 32) s += pr[i] * wr[i];
    #pragma unroll
    for (int o = 16; o > 0; o >>= 1) s += __shfl_down_sync(0xffffffffu, s, o);
    if (lane == 0) g_cvec[b * Dn + d] = s + ctx_b[d];
}

// ---------------- K2b: queries ----------------
__global__ void k_queries(const float* __restrict__ qp, float* __restrict__ out) {
    int idx = blockIdx.x * blockDim.x + threadIdx.x;
    int d = idx & 511, q = (idx >> 9) & 31, b = idx >> 14;
    float v = qp[q * Dn + d] + g_cvec[b * Dn + d];
    g_queries[idx] = v;
    out[OUT_QUER + idx] = v;
}

// ---------------- K2c: gates ----------------
__global__ void k_gates(const float* __restrict__ gate_w, const float* __restrict__ gate_b,
                        float* __restrict__ out) {
    int wg = blockIdx.x * 8 + (threadIdx.x >> 5);
    int lane = threadIdx.x & 31;
    int b = wg >> 5, q = wg & 31;
    const float* pr = g_pooled + b * Dn;
    const float* wr = gate_w + (size_t)q * Dn;
    float s = 0.f;
    for (int i = lane; i < Dn; i += 32) s += pr[i] * wr[i];
    #pragma unroll
    for (int o = 16; o > 0; o >>= 1) s += __shfl_down_sync(0xffffffffu, s, o);
    if (lane == 0) {
        float x = s + gate_b[q];
        float g = 1.0f / (1.0f + __expf(-x));
        g_gates[wg] = g;
        out[OUT_GATE + wg] = g;
    }
}

// ---------------- generic fp32 NT GEMM (small GEMMs), double-buffered ----------------
__global__ void __launch_bounds__(256)
gemm_nt(const float* __restrict__ A, int lda, long long sA,
        const float* __restrict__ Bm, int ldb, long long sB,
        float* __restrict__ C, int ldc, long long sC,
        int K,
        const float* __restrict__ colBias, long long sCB) {
    const int bn = blockIdx.x, bm = blockIdx.y, bz = blockIdx.z;
    const float* Ab = A + (size_t)bz * sA + (size_t)bm * 128 * lda;
    const float* Bb = Bm + (size_t)bz * sB + (size_t)bn * 64 * ldb;
    float* Cb = C + (size_t)bz * sC + (size_t)bm * 128 * ldc + (size_t)bn * 64;

    __shared__ float As[2][16][132];
    __shared__ float Bs[2][16][68];

    const int tid = threadIdx.x;
    const int tx = tid & 15;
    const int ty = tid >> 4;
    const int arow0 = tid >> 2, akq = tid & 3;
    const int bcol = tid >> 2, bkq = tid & 3;

    float acc[8][4];
    #pragma unroll
    for (int i = 0; i < 8; i++)
        #pragma unroll
        for (int j = 0; j < 4; j++) acc[i][j] = 0.f;

    {
        #pragma unroll
        for (int it = 0; it < 2; it++) {
            int row = arow0 + it * 64;
            float4 v = *(const float4*)(Ab + (size_t)row * lda + akq * 4);
            As[0][akq * 4 + 0][row] = v.x; As[0][akq * 4 + 1][row] = v.y;
            As[0][akq * 4 + 2][row] = v.z; As[0][akq * 4 + 3][row] = v.w;
        }
        float4 v = *(const float4*)(Bb + (size_t)bcol * ldb + bkq * 4);
        Bs[0][bkq * 4 + 0][bcol] = v.x; Bs[0][bkq * 4 + 1][bcol] = v.y;
        Bs[0][bkq * 4 + 2][bcol] = v.z; Bs[0][bkq * 4 + 3][bcol] = v.w;
    }
    __syncthreads();

    int buf = 0;
    for (int k0 = 0; k0 < K; k0 += 16) {
        const bool has_next = (k0 + 16) < K;
        float4 pa0, pa1, pb;
        if (has_next) {
            int kn = k0 + 16;
            pa0 = *(const float4*)(Ab + (size_t)(arow0)      * lda + kn + akq * 4);
            pa1 = *(const float4*)(Ab + (size_t)(arow0 + 64) * lda + kn + akq * 4);
            pb  = *(const float4*)(Bb + (size_t)bcol * ldb + kn + bkq * 4);
        }
        #pragma unroll
        for (int k = 0; k < 16; k++) {
            float a[8], b[4];
            #pragma unroll
            for (int i = 0; i < 8; i++) a[i] = As[buf][k][ty * 8 + i];
            #pragma unroll
            for (int j = 0; j < 4; j++) b[j] = Bs[buf][k][tx * 4 + j];
            #pragma unroll
            for (int i = 0; i < 8; i++)
                #pragma unroll
                for (int j = 0; j < 4; j++) acc[i][j] += a[i] * b[j];
        }
        if (has_next) {
            int nb = buf ^ 1;
            As[nb][akq * 4 + 0][arow0] = pa0.x; As[nb][akq * 4 + 1][arow0] = pa0.y;
            As[nb][akq * 4 + 2][arow0] = pa0.z; As[nb][akq * 4 + 3][arow0] = pa0.w;
            As[nb][akq * 4 + 0][arow0 + 64] = pa1.x; As[nb][akq * 4 + 1][arow0 + 64] = pa1.y;
            As[nb][akq * 4 + 2][arow0 + 64] = pa1.z; As[nb][akq * 4 + 3][arow0 + 64] = pa1.w;
            Bs[nb][bkq * 4 + 0][bcol] = pb.x; Bs[nb][bkq * 4 + 1][bcol] = pb.y;
            Bs[nb][bkq * 4 + 2][bcol] = pb.z; Bs[nb][bkq * 4 + 3][bcol] = pb.w;
            __syncthreads();
            buf = nb;
        }
    }

    #pragma unroll
    for (int i = 0; i < 8; i++) {
        int row = ty * 8 + i;
        #pragma unroll
        for (int j = 0; j < 4; j++) {
            int col = tx * 4 + j;
            float v = acc[i][j];
            if (colBias) v += colBias[bz * sCB + bn * 64 + col];
            Cb[(size_t)row * ldc + col] = v;
        }
    }
}

// ---------------- bf16x3 scores GEMM (m16n8k16) ----------------
// per batch bz: scores[256][8192] = qk[256][512] @ memory[8192][512]^T + sbias, masked
// CTA 128x64, BK=16, 8 warps 4m x 2n (warp tile 32x32); padded smem (conflict-free frags)
__global__ void __launch_bounds__(256)
gemm_bf16_scores(const float* __restrict__ memory) {
    const int bn = blockIdx.x, bm = blockIdx.y, bz = blockIdx.z;
    const float* Ab = g_qk + (size_t)bz * RROWS * Dn + (size_t)bm * 128 * Dn;
    const float* Bb = memory + (size_t)bz * Mn * Dn + (size_t)bn * 64 * Dn;
    float* Cb = g_attn + (size_t)bz * RROWS * Mn + (size_t)bm * 128 * Mn + bn * 64;

    __shared__ unsigned AsH[2][8][PADA], AsL[2][8][PADA];
    __shared__ unsigned BsH[2][8][PADB], BsL[2][8][PADB];

    const int tid = threadIdx.x;
    const int lane = tid & 31, warp = tid >> 5;
    const int wm = (warp & 3) * 32;
    const int wn = (warp >> 2) * 32;
    const int gid = lane >> 2, tig = lane & 3;

    const int arow0 = tid >> 2, akq = tid & 3;
    const int bcol = tid >> 2, bkq = tid & 3;

    float acc[2][4][4];
    #pragma unroll
    for (int mi = 0; mi < 2; mi++)
        #pragma unroll
        for (int ni = 0; ni < 4; ni++)
            #pragma unroll
            for (int j = 0; j < 4; j++) acc[mi][ni][j] = 0.f;

    {
        #pragma unroll
        for (int it = 0; it < 2; it++) {
            int row = arow0 + it * 64;
            float4 v = *(const float4*)(Ab + (size_t)row * Dn + akq * 4);
            unsigned h, l;
            pack2(v.x, v.y, h, l); AsH[0][akq * 2 + 0][row] = h; AsL[0][akq * 2 + 0][row] = l;
            pack2(v.z, v.w, h, l); AsH[0][akq * 2 + 1][row] = h; AsL[0][akq * 2 + 1][row] = l;
        }
        float4 v = *(const float4*)(Bb + (size_t)bcol * Dn + bkq * 4);
        unsigned h, l;
        pack2(v.x, v.y, h, l); BsH[0][bkq * 2 + 0][bcol] = h; BsL[0][bkq * 2 + 0][bcol] = l;
        pack2(v.z, v.w, h, l); BsH[0][bkq * 2 + 1][bcol] = h; BsL[0][bkq * 2 + 1][bcol] = l;
    }
    __syncthreads();

    int buf = 0;
    for (int k0 = 0; k0 < Dn; k0 += 16) {
        const bool has_next = (k0 + 16) < Dn;
        float4 pa0, pa1, pb;
        if (has_next) {
            int kn = k0 + 16;
            pa0 = *(const float4*)(Ab + (size_t)(arow0)      * Dn + kn + akq * 4);
            pa1 = *(const float4*)(Ab + (size_t)(arow0 + 64) * Dn + kn + akq * 4);
            pb  = *(const float4*)(Bb + (size_t)bcol * Dn + kn + bkq * 4);
        }

        unsigned ah[2][4], al[2][4];
        #pragma unroll
        for (int mi = 0; mi < 2; mi++) {
            int m0 = wm + mi * 16;
            ah[mi][0] = AsH[buf][tig][m0 + gid];     ah[mi][1] = AsH[buf][tig][m0 + gid + 8];
            ah[mi][2] = AsH[buf][tig + 4][m0 + gid]; ah[mi][3] = AsH[buf][tig + 4][m0 + gid + 8];
            al[mi][0] = AsL[buf][tig][m0 + gid];     al[mi][1] = AsL[buf][tig][m0 + gid + 8];
            al[mi][2] = AsL[buf][tig + 4][m0 + gid]; al[mi][3] = AsL[buf][tig + 4][m0 + gid + 8];
        }
        unsigned bh[4][2], bl[4][2];
        #pragma unroll
        for (int ni = 0; ni < 4; ni++) {
            int n0 = wn + ni * 8;
            bh[ni][0] = BsH[buf][tig][n0 + gid]; bh[ni][1] = BsH[buf][tig + 4][n0 + gid];
            bl[ni][0] = BsL[buf][tig][n0 + gid]; bl[ni][1] = BsL[buf][tig + 4][n0 + gid];
        }
        #pragma unroll
        for (int mi = 0; mi < 2; mi++)
            #pragma unroll
            for (int ni = 0; ni < 4; ni++) {
                mma_bf16(acc[mi][ni], ah[mi], bh[ni]);
                mma_bf16(acc[mi][ni], ah[mi], bl[ni]);
                mma_bf16(acc[mi][ni], al[mi], bh[ni]);
            }

        if (has_next) {
            int nb = buf ^ 1;
            unsigned h, l;
            pack2(pa0.x, pa0.y, h, l); AsH[nb][akq * 2 + 0][arow0] = h; AsL[nb][akq * 2 + 0][arow0] = l;
            pack2(pa0.z, pa0.w, h, l); AsH[nb][akq * 2 + 1][arow0] = h; AsL[nb][akq * 2 + 1][arow0] = l;
            pack2(pa1.x, pa1.y, h, l); AsH[nb][akq * 2 + 0][arow0 + 64] = h; AsL[nb][akq * 2 + 0][arow0 + 64] = l;
            pack2(pa1.z, pa1.w, h, l); AsH[nb][akq * 2 + 1][arow0 + 64] = h; AsL[nb][akq * 2 + 1][arow0 + 64] = l;
            pack2(pb.x, pb.y, h, l);   BsH[nb][bkq * 2 + 0][bcol] = h; BsL[nb][bkq * 2 + 0][bcol] = l;
            pack2(pb.z, pb.w, h, l);   BsH[nb][bkq * 2 + 1][bcol] = h; BsL[nb][bkq * 2 + 1][bcol] = l;
            __syncthreads();
            buf = nb;
        }
    }

    const float NEGINF = __int_as_float(0xff800000);
    #pragma unroll
    for (int mi = 0; mi < 2; mi++) {
        int r0 = wm + mi * 16 + gid;
        int r1 = r0 + 8;
        float sb0 = g_sbias[bz * RROWS + bm * 128 + r0];
        float sb1 = g_sbias[bz * RROWS + bm * 128 + r1];
        #pragma unroll
        for (int ni = 0; ni < 4; ni++) {
            int cl = wn + ni * 8 + tig * 2;
            int gc = bn * 64 + cl;
            unsigned char m0v = g_maskb[bz * Mn + gc];
            unsigned char m1v = g_maskb[bz * Mn + gc + 1];
            float2 v0, v1;
            v0.x = m0v ? acc[mi][ni][0] + sb0 : NEGINF;
            v0.y = m1v ? acc[mi][ni][1] + sb0 : NEGINF;
            v1.x = m0v ? acc[mi][ni][2] + sb1 : NEGINF;
            v1.y = m1v ? acc[mi][ni][3] + sb1 : NEGINF;
            *(float2*)(Cb + (size_t)r0 * Mn + cl) = v0;
            *(float2*)(Cb + (size_t)r1 * Mn + cl) = v1;
        }
    }
}

// ---------------- bf16x3 AM GEMM (m16n8k16), NN, BN=64 ----------------
// per batch b: AM[256][512] = attn[256][8192] @ memory[8192][512]
// CTA 128x64, BK=16, 8 warps 4m x 2n (warp tile 32x32); out layout [h][b][q][d]
__global__ void __launch_bounds__(256)
gemm_bf16_am(const float* __restrict__ memory) {
    const int bn = blockIdx.x, bm = blockIdx.y, b = blockIdx.z;   // bn<8
    const float* Ab = g_attn + (size_t)b * RROWS * Mn + (size_t)bm * 128 * Mn;
    const float* Bb = memory + (size_t)b * Mn * Dn + bn * 64;

    __shared__ unsigned AsH[2][8][PADA], AsL[2][8][PADA];
    __shared__ unsigned BsH[2][8][PADB], BsL[2][8][PADB];

    const int tid = threadIdx.x;
    const int lane = tid & 31, warp = tid >> 5;
    const int wm = (warp & 3) * 32;
    const int wn = (warp >> 2) * 32;
    const int gid = lane >> 2, tig = lane & 3;

    const int arow0 = tid >> 2, akq = tid & 3;
    const int bkp = tid >> 4, bq = tid & 15;      // tid<128: kpair 0..7, col-quad 0..15

    float acc[2][4][4];
    #pragma unroll
    for (int mi = 0; mi < 2; mi++)
        #pragma unroll
        for (int ni = 0; ni < 4; ni++)
            #pragma unroll
            for (int j = 0; j < 4; j++) acc[mi][ni][j] = 0.f;

    {
        #pragma unroll
        for (int it = 0; it < 2; it++) {
            int row = arow0 + it * 64;
            float4 v = *(const float4*)(Ab + (size_t)row * Mn + akq * 4);
            unsigned h, l;
            pack2(v.x, v.y, h, l); AsH[0][akq * 2 + 0][row] = h; AsL[0][akq * 2 + 0][row] = l;
            pack2(v.z, v.w, h, l); AsH[0][akq * 2 + 1][row] = h; AsL[0][akq * 2 + 1][row] = l;
        }
        if (tid < 128) {
            float4 v0 = *(const float4*)(Bb + (size_t)(2 * bkp)     * Dn + bq * 4);
            float4 v1 = *(const float4*)(Bb + (size_t)(2 * bkp + 1) * Dn + bq * 4);
            unsigned h, l;
            pack2(v0.x, v1.x, h, l); BsH[0][bkp][bq * 4 + 0] = h; BsL[0][bkp][bq * 4 + 0] = l;
            pack2(v0.y, v1.y, h, l); BsH[0][bkp][bq * 4 + 1] = h; BsL[0][bkp][bq * 4 + 1] = l;
            pack2(v0.z, v1.z, h, l); BsH[0][bkp][bq * 4 + 2] = h; BsL[0][bkp][bq * 4 + 2] = l;
            pack2(v0.w, v1.w, h, l); BsH[0][bkp][bq * 4 + 3] = h; BsL[0][bkp][bq * 4 + 3] = l;
        }
    }
    __syncthreads();

    int buf = 0;
    for (int k0 = 0; k0 < Mn; k0 += 16) {
        const bool has_next = (k0 + 16) < Mn;
        float4 pa0, pa1, pb0, pb1;
        if (has_next) {
            int kn = k0 + 16;
            pa0 = *(const float4*)(Ab + (size_t)(arow0)      * Mn + kn + akq * 4);
            pa1 = *(const float4*)(Ab + (size_t)(arow0 + 64) * Mn + kn + akq * 4);
            if (tid < 128) {
                pb0 = *(const float4*)(Bb + (size_t)(kn + 2 * bkp)     * Dn + bq * 4);
                pb1 = *(const float4*)(Bb + (size_t)(kn + 2 * bkp + 1) * Dn + bq * 4);
            }
        }

        unsigned ah[2][4], al[2][4];
        #pragma unroll
        for (int mi = 0; mi < 2; mi++) {
            int m0 = wm + mi * 16;
            ah[mi][0] = AsH[buf][tig][m0 + gid];     ah[mi][1] = AsH[buf][tig][m0 + gid + 8];
            ah[mi][2] = AsH[buf][tig + 4][m0 + gid]; ah[mi][3] = AsH[buf][tig + 4][m0 + gid + 8];
            al[mi][0] = AsL[buf][tig][m0 + gid];     al[mi][1] = AsL[buf][tig][m0 + gid + 8];
            al[mi][2] = AsL[buf][tig + 4][m0 + gid]; al[mi][3] = AsL[buf][tig + 4][m0 + gid + 8];
        }
        unsigned bh[4][2], bl[4][2];
        #pragma unroll
        for (int ni = 0; ni < 4; ni++) {
            int n0 = wn + ni * 8;
            bh[ni][0] = BsH[buf][tig][n0 + gid]; bh[ni][1] = BsH[buf][tig + 4][n0 + gid];
            bl[ni][0] = BsL[buf][tig][n0 + gid]; bl[ni][1] = BsL[buf][tig + 4][n0 + gid];
        }
        #pragma unroll
        for (int mi = 0; mi < 2; mi++)
            #pragma unroll
            for (int ni = 0; ni < 4; ni++) {
                mma_bf16(acc[mi][ni], ah[mi], bh[ni]);
                mma_bf16(acc[mi][ni], ah[mi], bl[ni]);
                mma_bf16(acc[mi][ni], al[mi], bh[ni]);
            }

        if (has_next) {
            int nb = buf ^ 1;
            unsigned h, l;
            pack2(pa0.x, pa0.y, h, l); AsH[nb][akq * 2 + 0][arow0] = h; AsL[nb][akq * 2 + 0][arow0] = l;
            pack2(pa0.z, pa0.w, h, l); AsH[nb][akq * 2 + 1][arow0] = h; AsL[nb][akq * 2 + 1][arow0] = l;
            pack2(pa1.x, pa1.y, h, l); AsH[nb][akq * 2 + 0][arow0 + 64] = h; AsL[nb][akq * 2 + 0][arow0 + 64] = l;
            pack2(pa1.z, pa1.w, h, l); AsH[nb][akq * 2 + 1][arow0 + 64] = h; AsL[nb][akq * 2 + 1][arow0 + 64] = l;
            if (tid < 128) {
                pack2(pb0.x, pb1.x, h, l); BsH[nb][bkp][bq * 4 + 0] = h; BsL[nb][bkp][bq * 4 + 0] = l;
                pack2(pb0.y, pb1.y, h, l); BsH[nb][bkp][bq * 4 + 1] = h; BsL[nb][bkp][bq * 4 + 1] = l;
                pack2(pb0.z, pb1.z, h, l); BsH[nb][bkp][bq * 4 + 2] = h; BsL[nb][bkp][bq * 4 + 2] = l;
                pack2(pb0.w, pb1.w, h, l); BsH[nb][bkp][bq * 4 + 3] = h; BsL[nb][bkp][bq * 4 + 3] = l;
            }
            __syncthreads();
            buf = nb;
        }
    }

    #pragma unroll
    for (int mi = 0; mi < 2; mi++) {
        #pragma unroll
        for (int p = 0; p < 2; p++) {
            int rl = wm + mi * 16 + gid + p * 8;
            int r = bm * 128 + rl;
            int h = r >> 5, q = r & 31;
            float* base = g_AM + (size_t)((h * Bn + b) * Qn + q) * Dn + bn * 64;
            #pragma unroll
            for (int ni = 0; ni < 4; ni++) {
                int cl = wn + ni * 8 + tig * 2;
                float2 v;
                v.x = acc[mi][ni][p * 2 + 0];
                v.y = acc[mi][ni][p * 2 + 1];
                *(float2*)(base + cl) = v;
            }
        }
    }
}

// ---------------- K3b: fold wk ----------------
__global__ void k_fold_qk(const float* __restrict__ in_w, const float* __restrict__ in_b) {
    int b = blockIdx.x >> 3, h = blockIdx.x & 7;
    int d = threadIdx.x;
    __shared__ float qs[Qn][HDn + 1];
    for (int l = threadIdx.x; l < Qn * HDn; l += blockDim.x) {
        int q = l >> 6, hd = l & 63;
        qs[q][hd] = g_qh[((size_t)(b * Qn + q)) * Dn + h * HDn + hd];
    }
    __syncthreads();

    float acc[Qn];
    #pragma unroll
    for (int q = 0; q < Qn; q++) acc[q] = 0.f;
    for (int hd = 0; hd < HDn; hd++) {
        float w = in_w[((size_t)(Dn + h * HDn + hd)) * Dn + d];
        #pragma unroll
        for (int q = 0; q < Qn; q++) acc[q] += qs[q][hd] * w;
    }
    float* outp = g_qk + (size_t)b * RROWS * Dn + (size_t)(h * Qn) * Dn + d;
    #pragma unroll
    for (int q = 0; q < Qn; q++) outp[(size_t)q * Dn] = SCALE * acc[q];

    if (threadIdx.x < Qn) {
        int q = threadIdx.x;
        float sb = 0.f;
        for (int hd = 0; hd < HDn; hd++) sb += qs[q][hd] * in_b[Dn + h * HDn + hd];
        g_sbias[b * RROWS + h * Qn + q] = SCALE * sb;
    }
}

// ---------------- K5: softmax (vectorized float4) ----------------
__global__ void __launch_bounds__(256) k_softmax() {
    __shared__ float4 buf[Mn / 4];
    __shared__ float red[256];
    int row = blockIdx.x;
    float4* base = (float4*)(g_attn + (size_t)row * Mn);
    int tid = threadIdx.x;

    float lmax = -INFINITY;
    for (int i = tid; i < Mn / 4; i += 256) {
        float4 v = base[i];
        buf[i] = v;
        lmax = fmaxf(lmax, fmaxf(fmaxf(v.x, v.y), fmaxf(v.z, v.w)));
    }
    red[tid] = lmax; __syncthreads();
    for (int s = 128; s > 0; s >>= 1) {
        if (tid < s) red[tid] = fmaxf(red[tid], red[tid + s]);
        __syncthreads();
    }
    float gmax = red[0]; __syncthreads();

    float lsum = 0.f;
    for (int i = tid; i < Mn / 4; i += 256) {
        float4 v = buf[i];
        v.x = __expf(v.x - gmax); v.y = __expf(v.y - gmax);
        v.z = __expf(v.z - gmax); v.w = __expf(v.w - gmax);
        buf[i] = v;
        lsum += v.x + v.y + v.z + v.w;
    }
    red[tid] = lsum; __syncthreads();
    for (int s = 128; s > 0; s >>= 1) {
        if (tid < s) red[tid] += red[tid + s];
        __syncthreads();
    }
    float inv = 1.0f / red[0];
    for (int i = tid; i < Mn / 4; i += 256) {
        float4 v = buf[i];
        v.x *= inv; v.y *= inv; v.z *= inv; v.w *= inv;
        base[i] = v;
    }
}

// ---------------- K6: attention = mean over heads (float4) ----------------
__global__ void k_attn_mean(float* __restrict__ out) {
    int gid = blockIdx.x * blockDim.x + threadIdx.x;
    int mv = gid & 2047, q = (gid >> 11) & 31, b = gid >> 16;
    const float4* base = (const float4*)(g_attn + (size_t)b * RROWS * Mn + (size_t)q * Mn) + mv;
    float4 s = make_float4(0.f, 0.f, 0.f, 0.f);
    #pragma unroll
    for (int h = 0; h < Hn; h++) {
        float4 v = base[(size_t)h * Qn * Mn / 4];
        s.x += v.x; s.y += v.y; s.z += v.z; s.w += v.w;
    }
    s.x *= 0.125f; s.y *= 0.125f; s.z *= 0.125f; s.w *= 0.125f;
    ((float4*)(out + OUT_ATTN))[((size_t)b * Qn + q) * (Mn / 4) + mv] = s;
}

// ---------------- K10: gate multiply + layernorm ----------------
__global__ void __launch_bounds__(256) k_gate_ln(const float* __restrict__ ln_g,
                                                const float* __restrict__ ln_b,
                                                float* __restrict__ out) {
    __shared__ float rbuf[Dn];
    __shared__ float red[256];
    int row = blockIdx.x;
    int tid = threadIdx.x;
    float g = g_gates[row];
    const float* rp = g_read + (size_t)row * Dn;

    float lsum = 0.f;
    for (int i = tid; i < Dn; i += 256) {
        float v = rp[i] * g;
        rbuf[i] = v;
        lsum += v;
    }
    red[tid] = lsum; __syncthreads();
    for (int s = 128; s > 0; s >>= 1) { if (tid < s) red[tid] += red[tid + s]; __syncthreads(); }
    float mu = red[0] * (1.0f / Dn); __syncthreads();

    float lv = 0.f;
    for (int i = tid; i < Dn; i += 256) {
        float d = rbuf[i] - mu;
        lv += d * d;
    }
    red[tid] = lv; __syncthreads();
    for (int s = 128; s > 0; s >>= 1) { if (tid < s) red[tid] += red[tid + s]; __syncthreads(); }
    float inv = rsqrtf(red[0] * (1.0f / Dn) + 1e-5f);

    for (int i = tid; i < Dn; i += 256)
        out[OUT_READ + (size_t)row * Dn + i] = (rbuf[i] - mu) * inv * ln_g[i] + ln_b[i];
}

// =============================== host launcher ===============================
extern "C" void kernel_launch(void* const* d_in, const int* in_sizes, int n_in,
                              void* d_out, int out_size) {
    const float* memory  = (const float*)d_in[0];
    const float* context = (const float*)d_in[1];
    const unsigned char* mask = (const unsigned char*)d_in[2];
    const float* qp      = (const float*)d_in[3];
    const float* ctx_w   = (const float*)d_in[4];
    const float* ctx_b   = (const float*)d_in[5];
    const float* in_w    = (const float*)d_in[6];
    const float* in_b    = (const float*)d_in[7];
    const float* out_w   = (const float*)d_in[8];
    const float* out_b   = (const float*)d_in[9];
    const float* ln_g    = (const float*)d_in[10];
    const float* ln_b    = (const float*)d_in[11];
    const float* gate_w  = (const float*)d_in[12];
    const float* gate_b  = (const float*)d_in[13];
    float* out = (float*)d_out;

    static float *p_queries = nullptr, *p_qh = nullptr, *p_AM = nullptr,
                 *p_ctx = nullptr, *p_read = nullptr;
    if (!p_queries) {
        cudaGetSymbolAddress((void**)&p_queries, g_queries);
        cudaGetSymbolAddress((void**)&p_qh, g_qh);
        cudaGetSymbolAddress((void**)&p_AM, g_AM);
        cudaGetSymbolAddress((void**)&p_ctx, g_ctx);
        cudaGetSymbolAddress((void**)&p_read, g_read);
    }

    // mask dtype sniff + normalize
    k_detect<<<1, 256>>>(mask);
    k_convert_mask<<<(Bn * Mn + 255) / 256, 256>>>(mask);

    // pooled / cvec / queries / gates
    k_pool<<<dim3(Bn, 8), 512>>>(context);
    k_cvec<<<512, 256>>>(ctx_w, ctx_b);
    k_queries<<<Bn * Qn * Dn / 256, 256>>>(qp, out);
    k_gates<<<32, 256>>>(gate_w, gate_b, out);

    // qh = queries @ wq^T + bq   (M=256, N=512, K=512)
    gemm_nt<<<dim3(Dn / 64, 2, 1), 256>>>(
        p_queries, Dn, 0, in_w, Dn, 0, p_qh, Dn, 0, Dn, in_b, 0);

    // fold wk: qk, sbias
    k_fold_qk<<<Bn * Hn, Dn>>>(in_w, in_b);

    // scores = qk @ memory^T + sbias, masked  (bf16x3 tensor cores)
    gemm_bf16_scores<<<dim3(Mn / 64, 2, Bn), 256>>>(memory);

    // softmax rows
    k_softmax<<<Bn * RROWS, 256>>>();

    // attention = mean over heads -> out
    k_attn_mean<<<Bn * Qn * (Mn / 4) / 256, 256>>>(out);

    // AM = attn @ memory  (bf16x3 tensor cores, BN=64)
    gemm_bf16_am<<<dim3(Dn / 64, 2, Bn), 256>>>(memory);

    // ctx = AM_h @ wv_h^T + bv_h  (batched over heads: 256 x 64, K=512)
    gemm_nt<<<dim3(1, 2, Hn), 256>>>(
        p_AM, Dn, (long long)Bn * Qn * Dn,
        in_w + (size_t)2 * Dn * Dn, Dn, (long long)HDn * Dn,
        p_ctx, Dn, (long long)HDn, Dn,
        in_b + 2 * Dn, HDn);

    // readouts = ctx @ out_w^T + out_b  (256 x 512, K=512)
    gemm_nt<<<dim3(Dn / 64, 2, 1), 256>>>(
        p_ctx, Dn, 0, out_w, Dn, 0, p_read, Dn, 0, Dn, out_b, 0);

    // gate + layernorm -> out
    k_gate_ln<<<Bn * Qn, 256>>>(ln_g, ln_b, out);
}